// round 13
// baseline (speedup 1.0000x reference)
#include <cuda_runtime.h>
#include <cuda_fp16.h>

#define NN 100000
#define NNP 100096            // padded to multiple of 128 (782 * 128)
#define NE 1600000

// ---- scratch (static device globals; zero-initialized; no allocation allowed) ----
__device__ __half g_xh[NNP * 128];      // x hi/lo (fp16 split, padded)
__device__ __half g_xl[NNP * 128];
__device__ __half g_hNh[NNP * 256];     // aggregated neighbor feats hi/lo
__device__ __half g_hNl[NNP * 256];
__device__ float  g_acc[NNP * 256];     // self-GEMM partial (reused L1, L2)
__device__ __half g_hAh[NNP * 256];     // layer-1 output hi/lo
__device__ __half g_hAl[NNP * 256];
__device__ __half g_hBh[NNP * 256];     // layer-2 output hi/lo
__device__ __half g_hBl[NNP * 256];
__device__ float  g_z[NNP * 128];       // layer-3 GEMM out: [z_self | z_neigh]
__device__ __half g_W1sh[256 * 128];    // W1 self half, packed
__device__ __half g_W1sl[256 * 128];
__device__ __half g_W1nh[256 * 128];    // W1 neighbor half, packed
__device__ __half g_W1nl[256 * 128];
__device__ __half g_W2sh[256 * 256];
__device__ __half g_W2sl[256 * 256];
__device__ __half g_W2nh[256 * 256];
__device__ __half g_W2nl[256 * 256];
__device__ __half g_W3h[128 * 256];     // stacked [W3_self; W3_neigh]
__device__ __half g_W3l[128 * 256];
__device__ int   g_deg[NN];             // zero at launch entry (static init +
                                        // re-zeroed by k_csr_mid each launch)
__device__ int   g_rowptr[NN + 1];
__device__ int   g_cursor[NN];
__device__ int   g_csr[NE];

// ---- host-side stream/event resources (created once at program start) ----
static cudaStream_t g_s2;
static cudaEvent_t g_ev0, g_ev1, g_ev2, g_ev3;
struct StreamInit {
    StreamInit() {
        cudaStreamCreateWithFlags(&g_s2, cudaStreamNonBlocking);
        cudaEventCreateWithFlags(&g_ev0, cudaEventDisableTiming);
        cudaEventCreateWithFlags(&g_ev1, cudaEventDisableTiming);
        cudaEventCreateWithFlags(&g_ev2, cudaEventDisableTiming);
        cudaEventCreateWithFlags(&g_ev3, cudaEventDisableTiming);
    }
};
static StreamInit g_stream_init;

// ======================= helpers =======================

__device__ __forceinline__ void splith(float v, __half& h, __half& l) {
    h = __float2half_rn(v);
    l = __float2half_rn(v - __half2float(h));
}

__device__ __forceinline__ unsigned smem_u32(const void* p) {
    unsigned a;
    asm("{ .reg .u64 t; cvta.to.shared.u64 t, %1; cvt.u32.u64 %0, t; }" : "=r"(a) : "l"(p));
    return a;
}

__device__ __forceinline__ void cp16(unsigned dst, const void* src) {
    asm volatile("cp.async.cg.shared.global [%0], [%1], 16;" :: "r"(dst), "l"(src));
}
#define CP_COMMIT() asm volatile("cp.async.commit_group;" ::: "memory")
#define CP_WAIT1()  asm volatile("cp.async.wait_group 1;" ::: "memory")
#define CP_WAIT0()  asm volatile("cp.async.wait_group 0;" ::: "memory")

__device__ __forceinline__ void mma16(float* c, const unsigned* a, const unsigned* b) {
    asm volatile(
        "mma.sync.aligned.m16n8k16.row.col.f32.f16.f16.f32 "
        "{%0,%1,%2,%3}, {%4,%5,%6,%7}, {%8,%9}, {%0,%1,%2,%3};"
        : "+f"(c[0]), "+f"(c[1]), "+f"(c[2]), "+f"(c[3])
        : "r"(a[0]), "r"(a[1]), "r"(a[2]), "r"(a[3]), "r"(b[0]), "r"(b[1]));
}

__device__ __forceinline__ void ldm_x4(unsigned& r0, unsigned& r1, unsigned& r2,
                                       unsigned& r3, unsigned addr) {
    asm volatile("ldmatrix.sync.aligned.m8n8.x4.shared.b16 {%0,%1,%2,%3}, [%4];"
                 : "=r"(r0), "=r"(r1), "=r"(r2), "=r"(r3) : "r"(addr));
}

// ======================= fused prep: x split, packed W splits, dst histogram =======================

__global__ void k_prep(const float* __restrict__ x, const float* __restrict__ W1,
                       const float* __restrict__ W2, const float* __restrict__ W3,
                       const int* __restrict__ dst) {
    const int NX = NN * 32;                    // float4 count of x
    long i = (long)blockIdx.x * blockDim.x + threadIdx.x;
    if (i < NX) {
        float4 v = ((const float4*)x)[i];
        __half h0, h1, h2, h3, l0, l1, l2, l3;
        splith(v.x, h0, l0); splith(v.y, h1, l1);
        splith(v.z, h2, l2); splith(v.w, h3, l3);
        ((__half2*)g_xh)[2 * i]     = __halves2half2(h0, h1);
        ((__half2*)g_xh)[2 * i + 1] = __halves2half2(h2, h3);
        ((__half2*)g_xl)[2 * i]     = __halves2half2(l0, l1);
        ((__half2*)g_xl)[2 * i + 1] = __halves2half2(l2, l3);
        return;
    }
    i -= NX;
    if (i < 256 * 256) {                       // W1 split + pack self/neigh halves
        int r = (int)(i >> 8), c = (int)(i & 255);
        __half h, l; splith(W1[i], h, l);
        if (c < 128) { g_W1sh[r * 128 + c] = h; g_W1sl[r * 128 + c] = l; }
        else         { g_W1nh[r * 128 + c - 128] = h; g_W1nl[r * 128 + c - 128] = l; }
        return;
    }
    i -= 256 * 256;
    if (i < 256 * 512) {                       // W2 split + pack
        int r = (int)(i >> 9), c = (int)(i & 511);
        __half h, l; splith(W2[i], h, l);
        if (c < 256) { g_W2sh[r * 256 + c] = h; g_W2sl[r * 256 + c] = l; }
        else         { g_W2nh[r * 256 + c - 256] = h; g_W2nl[r * 256 + c - 256] = l; }
        return;
    }
    i -= 256 * 512;
    if (i < 128 * 256) {                       // W3 stacked [self; neigh]
        int r = (int)(i >> 8), c = (int)(i & 255);
        float v = (r < 64) ? W3[r * 512 + c] : W3[(r - 64) * 512 + 256 + c];
        __half h, l; splith(v, h, l);
        g_W3h[i] = h; g_W3l[i] = l;
        return;
    }
    i -= 128 * 256;
    if (i < NE) atomicAdd(&g_deg[dst[i]], 1);  // histogram
}

#define PREP_TOTAL (NN * 32 + 256 * 256 + 256 * 512 + 128 * 256 + NE)

// ======================= CSR mid: scan + fill (+ re-zero deg for next launch) =======================

#define MIDT 1024
#define CH2 ((NN + MIDT - 1) / MIDT)   // 98

__global__ void __launch_bounds__(MIDT)
k_csr_mid() {
    __shared__ int sp[MIDT];
    int t = threadIdx.x;
    int base = t * CH2;
    int end = base + CH2; if (end > NN) end = NN;

    int s = 0;
    for (int i = base; i < end; i++) s += g_deg[i];
    sp[t] = s;
    __syncthreads();

#pragma unroll
    for (int off = 1; off < MIDT; off <<= 1) {
        int v = (t >= off) ? sp[t - off] : 0;
        __syncthreads();
        sp[t] += v;
        __syncthreads();
    }
    int run = sp[t] - s;                       // exclusive prefix
    if (t == MIDT - 1) g_rowptr[NN] = sp[MIDT - 1];

    for (int i = base; i < end; i++) {
        g_rowptr[i] = run;
        g_cursor[i] = run;
        run += g_deg[i];
        g_deg[i] = 0;                          // invariant for next launch
    }
}

__global__ void k_scatter(const int* __restrict__ src, const int* __restrict__ dst) {
    int e = blockIdx.x * blockDim.x + threadIdx.x;
    if (e < NE) {
        int p = atomicAdd(&g_cursor[dst[e]], 1);
        g_csr[p] = src[e];
    }
}

// ======================= aggregation from fp32 source (layer 1) =======================

template <int DV, int UNR>
__global__ void k_agg(const float* __restrict__ h, __half* __restrict__ oh,
                      __half* __restrict__ ol) {
    int gwarp = (blockIdx.x * blockDim.x + threadIdx.x) >> 5;
    int lane = threadIdx.x & 31;
    if (gwarp >= NN) return;

    int s0 = g_rowptr[gwarp];
    int s1 = g_rowptr[gwarp + 1];

    float4 acc[DV];
#pragma unroll
    for (int j = 0; j < DV; j++) acc[j] = make_float4(0.f, 0.f, 0.f, 0.f);

    const int stride4 = DV * 32;
    const float4* __restrict__ hv = (const float4*)h;

    int e = s0;
    for (; e + UNR <= s1; e += UNR) {
        float4 v[UNR][DV];
#pragma unroll
        for (int u = 0; u < UNR; u++) {
            const float4* r = hv + (long)g_csr[e + u] * stride4;
#pragma unroll
            for (int j = 0; j < DV; j++) v[u][j] = r[lane + 32 * j];
        }
#pragma unroll
        for (int u = 0; u < UNR; u++)
#pragma unroll
            for (int j = 0; j < DV; j++) {
                acc[j].x += v[u][j].x; acc[j].y += v[u][j].y;
                acc[j].z += v[u][j].z; acc[j].w += v[u][j].w;
            }
    }
    for (; e < s1; e++) {
        const float4* r = hv + (long)g_csr[e] * stride4;
#pragma unroll
        for (int j = 0; j < DV; j++) {
            float4 v = r[lane + 32 * j];
            acc[j].x += v.x; acc[j].y += v.y; acc[j].z += v.z; acc[j].w += v.w;
        }
    }

    int deg = s1 - s0;
    float inv = 1.0f / (float)(deg > 0 ? deg : 1);
    __half2* ovh = (__half2*)oh + (long)gwarp * (stride4 * 2);
    __half2* ovl = (__half2*)ol + (long)gwarp * (stride4 * 2);
#pragma unroll
    for (int j = 0; j < DV; j++) {
        float4 v;
        v.x = acc[j].x * inv; v.y = acc[j].y * inv;
        v.z = acc[j].z * inv; v.w = acc[j].w * inv;
        __half h0, h1, h2, h3, l0, l1, l2, l3;
        splith(v.x, h0, l0); splith(v.y, h1, l1);
        splith(v.z, h2, l2); splith(v.w, h3, l3);
        int f = lane + 32 * j;
        ovh[2 * f]     = __halves2half2(h0, h1);
        ovh[2 * f + 1] = __halves2half2(h2, h3);
        ovl[2 * f]     = __halves2half2(l0, l1);
        ovl[2 * f + 1] = __halves2half2(l2, l3);
    }
}

// ======================= aggregation from hi/lo fp16 planes (layer 2, 256-dim) =======================

__device__ __forceinline__ void acc8(float* a, uint4 h, uint4 l) {
    const unsigned* hp = (const unsigned*)&h;
    const unsigned* lp = (const unsigned*)&l;
#pragma unroll
    for (int q = 0; q < 4; q++) {
        float2 fh = __half22float2(*(const __half2*)&hp[q]);
        float2 fl = __half22float2(*(const __half2*)&lp[q]);
        a[2 * q]     += fh.x + fl.x;
        a[2 * q + 1] += fh.y + fl.y;
    }
}

__global__ void k_agg_hl(const __half* __restrict__ hi, const __half* __restrict__ lo,
                         __half* __restrict__ oh, __half* __restrict__ ol) {
    int gwarp = (blockIdx.x * blockDim.x + threadIdx.x) >> 5;
    int lane = threadIdx.x & 31;
    if (gwarp >= NN) return;

    int s0 = g_rowptr[gwarp];
    int s1 = g_rowptr[gwarp + 1];

    float acc[8];
#pragma unroll
    for (int q = 0; q < 8; q++) acc[q] = 0.f;

    const uint4* hv = (const uint4*)hi;        // 32 uint4 per 256-half row
    const uint4* lv = (const uint4*)lo;

    int e = s0;
    for (; e + 2 <= s1; e += 2) {
        long ra = (long)g_csr[e] * 32, rb = (long)g_csr[e + 1] * 32;
        uint4 ha = hv[ra + lane], la = lv[ra + lane];
        uint4 hb = hv[rb + lane], lb = lv[rb + lane];
        acc8(acc, ha, la);
        acc8(acc, hb, lb);
    }
    if (e < s1) {
        long ra = (long)g_csr[e] * 32;
        acc8(acc, hv[ra + lane], lv[ra + lane]);
    }

    int deg = s1 - s0;
    float inv = 1.0f / (float)(deg > 0 ? deg : 1);
    __half2* ovh = (__half2*)oh + (long)gwarp * 128 + lane * 4;
    __half2* ovl = (__half2*)ol + (long)gwarp * 128 + lane * 4;
#pragma unroll
    for (int q = 0; q < 4; q++) {
        float v0 = acc[2 * q] * inv, v1 = acc[2 * q + 1] * inv;
        __half h0, h1, l0, l1;
        splith(v0, h0, l0); splith(v1, h1, l1);
        ovh[q] = __halves2half2(h0, h1);
        ovl[q] = __halves2half2(l0, l1);
    }
}

// ======================= fp16 3-product GEMM (2-stage; last-chunk wait FIXED) =======================
// C[M, N_OUT] = A @ W^T (+bias / +Cacc, optional ReLU), as hi.hi + hi.lo + lo.hi.
// A: [NNP, K] fp16 planes; W: [*, K] packed contiguous, row stride K.
// OMODE: 0 = fp32 Cf only, 2 = fp16 splits only.
// NOTE: final iteration must wait_group 0 — wait_group 1 does NOT guarantee the
// last-committed chunk has landed (race manifests under concurrent kernels).

template <int N_OUT, int K, bool RELU, int OMODE, bool ACCUM, bool HAS_BIAS>
__global__ void __launch_bounds__(256, 2)
k_mma(const __half* __restrict__ Ah, const __half* __restrict__ Al,
      const __half* __restrict__ Wh, const __half* __restrict__ Wl,
      const float* __restrict__ bias, const float* __restrict__ Cacc,
      float* __restrict__ Cf, __half* __restrict__ Ch, __half* __restrict__ Cl) {
    constexpr int NCP = K / 64;
    constexpr int NC3 = 3 * NCP;
    constexpr int NT = 8;
    constexpr int SH = 72;
    constexpr int A_BYTES = 128 * SH * 2;      // 18432
    constexpr int STAGE_B = 2 * A_BYTES;

    extern __shared__ char smem_raw[];
    const unsigned sbase = smem_u32(smem_raw);
    const int tid = threadIdx.x;
    const int wid = tid >> 5;
    const int lane = tid & 31;
    const int wm = wid & 3;
    const int wn = wid >> 2;
    const int n0 = blockIdx.x * 128;
    const int m0 = blockIdx.y * 128;

    const int lr = lane >> 2;
    const int lc = lane & 3;

    unsigned offA[2], offB[4];
#pragma unroll
    for (int mt = 0; mt < 2; mt++) {
        int row = wm * 32 + mt * 16 + (lane & 15);
        int col = (lane >> 4) * 8;
        offA[mt] = (unsigned)(row * SH + col) * 2;
    }
#pragma unroll
    for (int p = 0; p < 4; p++) {
        int row = wn * 64 + p * 16 + (lane & 7) + ((lane >> 4) & 1) * 8;
        int col = ((lane >> 3) & 1) * 8;
        offB[p] = (unsigned)(A_BYTES) + (unsigned)(row * SH + col) * 2;
    }

    float acc[2][NT][4];
#pragma unroll
    for (int mt = 0; mt < 2; mt++)
#pragma unroll
        for (int nt = 0; nt < NT; nt++)
#pragma unroll
            for (int q = 0; q < 4; q++) acc[mt][nt][q] = 0.f;

    auto load_chunk = [&](int j, int s) {
        unsigned base = sbase + s * STAGE_B;
        int p = j / NCP;                       // 0: hi.hi, 1: hi.lo, 2: lo.hi
        int k0 = (j - p * NCP) * 64;
        const __half* A = (p < 2) ? Ah : Al;
        const __half* B = (p == 1) ? Wl : Wh;
#pragma unroll
        for (int q = 0; q < 4; q++) {
            int idx = tid + 256 * q;
            int row = idx >> 3, c8 = idx & 7;
            cp16(base + (unsigned)(row * (SH * 2) + c8 * 16),
                 A + (long)(m0 + row) * K + k0 + c8 * 8);
        }
#pragma unroll
        for (int q = 0; q < 4; q++) {
            int idx = tid + 256 * q;
            int n = idx >> 3, c8 = idx & 7;
            cp16(base + (unsigned)(A_BYTES + n * (SH * 2) + c8 * 16),
                 B + (long)(n0 + n) * K + k0 + c8 * 8);
        }
        CP_COMMIT();
    };

    load_chunk(0, 0);
    load_chunk(1, 1);

#pragma unroll 1
    for (int i = 0; i < NC3; i++) {
        int s = i & 1;
        if (i == NC3 - 1) { CP_WAIT0(); } else { CP_WAIT1(); }
        __syncthreads();

        unsigned stage = sbase + s * STAGE_B;

#pragma unroll
        for (int ks = 0; ks < 4; ks++) {
            unsigned kso = ks * 32;
            unsigned a[2][4];
#pragma unroll
            for (int mt = 0; mt < 2; mt++)
                ldm_x4(a[mt][0], a[mt][1], a[mt][2], a[mt][3],
                       stage + offA[mt] + kso);
            unsigned b[NT][2];
#pragma unroll
            for (int p = 0; p < 4; p++)
                ldm_x4(b[2 * p][0], b[2 * p][1], b[2 * p + 1][0], b[2 * p + 1][1],
                       stage + offB[p] + kso);
#pragma unroll
            for (int mt = 0; mt < 2; mt++)
#pragma unroll
                for (int nt = 0; nt < NT; nt++)
                    mma16(acc[mt][nt], a[mt], b[nt]);
        }

        __syncthreads();
        if (i + 2 < NC3) load_chunk(i + 2, s);
    }

    // epilogue
#pragma unroll
    for (int mt = 0; mt < 2; mt++) {
#pragma unroll
        for (int nt = 0; nt < NT; nt++) {
            int n = n0 + wn * 64 + nt * 8 + lc * 2;
            float b0 = 0.f, b1 = 0.f;
            if (HAS_BIAS) { b0 = bias[n]; b1 = bias[n + 1]; }
            int r0 = m0 + wm * 32 + mt * 16 + lr;
#pragma unroll
            for (int h = 0; h < 2; h++) {
                int r = r0 + h * 8;
                if (r < NN) {
                    long off = (long)r * N_OUT + n;
                    float v0 = acc[mt][nt][2 * h + 0] + b0;
                    float v1 = acc[mt][nt][2 * h + 1] + b1;
                    if (ACCUM) {
                        float2 pv = *(const float2*)(Cacc + off);
                        v0 += pv.x; v1 += pv.y;
                    }
                    if (RELU) { v0 = v0 > 0.f ? v0 : 0.f; v1 = v1 > 0.f ? v1 : 0.f; }
                    if (OMODE == 0) {
                        *(float2*)(Cf + off) = make_float2(v0, v1);
                    } else {
                        __half h0, h1, l0, l1;
                        splith(v0, h0, l0); splith(v1, h1, l1);
                        ((__half2*)Ch)[off >> 1] = __halves2half2(h0, h1);
                        ((__half2*)Cl)[off >> 1] = __halves2half2(l0, l1);
                    }
                }
            }
        }
    }
}

// ======================= layer-3 final: out = z_self + mean(z_neigh) + b =======================

__global__ void k_agg_out(const float* __restrict__ z, const float* __restrict__ b3,
                          float* __restrict__ out) {
    int gwarp = (blockIdx.x * blockDim.x + threadIdx.x) >> 5;
    int lane = threadIdx.x & 31;
    if (gwarp >= NN) return;

    int s0 = g_rowptr[gwarp];
    int s1 = g_rowptr[gwarp + 1];

    float2 acc = make_float2(0.f, 0.f);
    const float2* zn = (const float2*)(z + 64);
    int e = s0;
    for (; e + 3 < s1; e += 4) {
        float2 v0 = zn[(long)g_csr[e] * 64 + lane];
        float2 v1 = zn[(long)g_csr[e + 1] * 64 + lane];
        float2 v2 = zn[(long)g_csr[e + 2] * 64 + lane];
        float2 v3 = zn[(long)g_csr[e + 3] * 64 + lane];
        acc.x += (v0.x + v1.x) + (v2.x + v3.x);
        acc.y += (v0.y + v1.y) + (v2.y + v3.y);
    }
    for (; e < s1; e++) {
        float2 v = zn[(long)g_csr[e] * 64 + lane];
        acc.x += v.x; acc.y += v.y;
    }
    int deg = s1 - s0;
    float inv = 1.0f / (float)(deg > 0 ? deg : 1);

    float2 self = ((const float2*)z)[(long)gwarp * 64 + lane];
    float2 bb = ((const float2*)b3)[lane];
    float2 r;
    r.x = self.x + acc.x * inv + bb.x;
    r.y = self.y + acc.y * inv + bb.y;
    ((float2*)out)[(long)gwarp * 32 + lane] = r;
}

// ======================= launch =======================

extern "C" void kernel_launch(void* const* d_in, const int* in_sizes, int n_in,
                              void* d_out, int out_size) {
    const float* x   = (const float*)d_in[0];
    const int*   src = (const int*)d_in[1];
    const int*   dst = (const int*)d_in[2];
    const float* W1  = (const float*)d_in[3];
    const float* b1  = (const float*)d_in[4];
    const float* W2  = (const float*)d_in[5];
    const float* b2  = (const float*)d_in[6];
    const float* W3  = (const float*)d_in[7];
    const float* b3  = (const float*)d_in[8];
    float* out = (float*)d_out;

    __half *xh, *xl, *hNh, *hNl, *hAh, *hAl, *hBh, *hBl;
    __half *W1sh, *W1sl, *W1nh, *W1nl, *W2sh, *W2sl, *W2nh, *W2nl, *W3h, *W3l;
    float *acc, *z;
    cudaGetSymbolAddress((void**)&xh, g_xh);
    cudaGetSymbolAddress((void**)&xl, g_xl);
    cudaGetSymbolAddress((void**)&hNh, g_hNh);
    cudaGetSymbolAddress((void**)&hNl, g_hNl);
    cudaGetSymbolAddress((void**)&acc, g_acc);
    cudaGetSymbolAddress((void**)&hAh, g_hAh);
    cudaGetSymbolAddress((void**)&hAl, g_hAl);
    cudaGetSymbolAddress((void**)&hBh, g_hBh);
    cudaGetSymbolAddress((void**)&hBl, g_hBl);
    cudaGetSymbolAddress((void**)&z, g_z);
    cudaGetSymbolAddress((void**)&W1sh, g_W1sh);
    cudaGetSymbolAddress((void**)&W1sl, g_W1sl);
    cudaGetSymbolAddress((void**)&W1nh, g_W1nh);
    cudaGetSymbolAddress((void**)&W1nl, g_W1nl);
    cudaGetSymbolAddress((void**)&W2sh, g_W2sh);
    cudaGetSymbolAddress((void**)&W2sl, g_W2sl);
    cudaGetSymbolAddress((void**)&W2nh, g_W2nh);
    cudaGetSymbolAddress((void**)&W2nl, g_W2nl);
    cudaGetSymbolAddress((void**)&W3h, g_W3h);
    cudaGetSymbolAddress((void**)&W3l, g_W3l);

    constexpr int SMB = 2 * 2 * 128 * 72 * 2;   // 73728
    cudaFuncSetAttribute(k_mma<256, 128, false, 0, false, true>,
                         cudaFuncAttributeMaxDynamicSharedMemorySize, SMB);
    cudaFuncSetAttribute(k_mma<256, 128, true,  2, true,  false>,
                         cudaFuncAttributeMaxDynamicSharedMemorySize, SMB);
    cudaFuncSetAttribute(k_mma<256, 256, false, 0, false, true>,
                         cudaFuncAttributeMaxDynamicSharedMemorySize, SMB);
    cudaFuncSetAttribute(k_mma<256, 256, true,  2, true,  false>,
                         cudaFuncAttributeMaxDynamicSharedMemorySize, SMB);
    cudaFuncSetAttribute(k_mma<128, 256, false, 0, false, false>,
                         cudaFuncAttributeMaxDynamicSharedMemorySize, SMB);

    const int AGG_BLOCKS = (NN + 7) / 8;
    const int GM = NNP / 128;   // 782

    // --- prep (splits + histogram) ---
    k_prep<<<(PREP_TOTAL + 255) / 256, 256>>>(x, W1, W2, W3, dst);

    // fork: L1 self-GEMM on s2 (needs only prep outputs)
    cudaEventRecord(g_ev0, 0);
    cudaStreamWaitEvent(g_s2, g_ev0, 0);
    k_mma<256, 128, false, 0, false, true><<<dim3(2, GM), 256, SMB, g_s2>>>(
        xh, xl, W1sh, W1sl, b1, nullptr, acc, nullptr, nullptr);

    // main stream: CSR + L1 aggregation (overlaps with L1 self-GEMM)
    k_csr_mid<<<1, MIDT>>>();
    k_scatter<<<(NE + 255) / 256, 256>>>(src, dst);
    k_agg<1, 4><<<AGG_BLOCKS, 256>>>(x, hNh, hNl);

    // join; L1 neighbor GEMM: hA = relu(acc + hN @ W1n^T) -> splits
    cudaEventRecord(g_ev1, g_s2);
    cudaStreamWaitEvent(0, g_ev1, 0);
    k_mma<256, 128, true, 2, true, false><<<dim3(2, GM), 256, SMB>>>(
        hNh, hNl, W1nh, W1nl, nullptr, acc, nullptr, hAh, hAl);

    // fork: L2 self-GEMM on s2 (needs hA)
    cudaEventRecord(g_ev2, 0);
    cudaStreamWaitEvent(g_s2, g_ev2, 0);
    k_mma<256, 256, false, 0, false, true><<<dim3(2, GM), 256, SMB, g_s2>>>(
        hAh, hAl, W2sh, W2sl, b2, nullptr, acc, nullptr, nullptr);

    // main stream: L2 aggregation (overlaps with L2 self-GEMM)
    k_agg_hl<<<AGG_BLOCKS, 256>>>(hAh, hAl, hNh, hNl);

    // join; L2 neighbor GEMM: hB = relu(acc + hN @ W2n^T) -> splits
    cudaEventRecord(g_ev3, g_s2);
    cudaStreamWaitEvent(0, g_ev3, 0);
    k_mma<256, 256, true, 2, true, false><<<dim3(2, GM), 256, SMB>>>(
        hNh, hNl, W2nh, W2nl, nullptr, acc, nullptr, hBh, hBl);

    // L3 (linear-reordered): z = hB @ [W3_self; W3_neigh]^T, then combine
    k_mma<128, 256, false, 0, false, false><<<dim3(1, GM), 256, SMB>>>(
        hBh, hBl, W3h, W3l, nullptr, nullptr, z, nullptr, nullptr);
    k_agg_out<<<AGG_BLOCKS, 256>>>(z, b3, out);
}

// round 14
// speedup vs baseline: 1.1442x; 1.1442x over previous
#include <cuda_runtime.h>
#include <cuda_fp16.h>

#define NN 100000
#define NNP 100096            // padded to multiple of 128 (782 * 128)
#define NE 1600000

// ---- scratch (static device globals; zero-initialized; no allocation allowed) ----
__device__ __half g_xh[NNP * 128];      // x hi/lo (fp16 split, padded)
__device__ __half g_xl[NNP * 128];
__device__ __half g_hNh[NNP * 256];     // aggregated neighbor feats hi/lo
__device__ __half g_hNl[NNP * 256];
__device__ __half g_hAh[NNP * 256];     // layer-1 output hi/lo
__device__ __half g_hAl[NNP * 256];
__device__ __half g_hBh[NNP * 256];     // layer-2 output hi/lo
__device__ __half g_hBl[NNP * 256];
__device__ float  g_z[NNP * 128];       // layer-3 GEMM out: [z_self | z_neigh]
__device__ __half g_W1h[256 * 256];
__device__ __half g_W1l[256 * 256];
__device__ __half g_W2h[256 * 512];
__device__ __half g_W2l[256 * 512];
__device__ __half g_W3h[128 * 256];     // stacked [W3_self; W3_neigh]
__device__ __half g_W3l[128 * 256];
__device__ int   g_deg[NN];             // zero at launch entry (static init +
                                        // re-zeroed by k_csr_mid each launch)
__device__ int   g_rowptr[NN + 1];
__device__ int   g_cursor[NN];
__device__ int   g_csr[NE];

// ---- host-side stream/event resources (created once at program start) ----
static cudaStream_t g_s2;
static cudaEvent_t g_ev0, g_ev1;
struct StreamInit {
    StreamInit() {
        cudaStreamCreateWithFlags(&g_s2, cudaStreamNonBlocking);
        cudaEventCreateWithFlags(&g_ev0, cudaEventDisableTiming);
        cudaEventCreateWithFlags(&g_ev1, cudaEventDisableTiming);
    }
};
static StreamInit g_stream_init;

// ======================= helpers =======================

__device__ __forceinline__ void splith(float v, __half& h, __half& l) {
    h = __float2half_rn(v);
    l = __float2half_rn(v - __half2float(h));
}

__device__ __forceinline__ unsigned smem_u32(const void* p) {
    unsigned a;
    asm("{ .reg .u64 t; cvta.to.shared.u64 t, %1; cvt.u32.u64 %0, t; }" : "=r"(a) : "l"(p));
    return a;
}

__device__ __forceinline__ void cp16(unsigned dst, const void* src) {
    asm volatile("cp.async.cg.shared.global [%0], [%1], 16;" :: "r"(dst), "l"(src));
}
#define CP_COMMIT() asm volatile("cp.async.commit_group;" ::: "memory")
#define CP_WAIT1()  asm volatile("cp.async.wait_group 1;" ::: "memory")
#define CP_WAIT0()  asm volatile("cp.async.wait_group 0;" ::: "memory")

__device__ __forceinline__ void mma16(float* c, const unsigned* a, const unsigned* b) {
    asm volatile(
        "mma.sync.aligned.m16n8k16.row.col.f32.f16.f16.f32 "
        "{%0,%1,%2,%3}, {%4,%5,%6,%7}, {%8,%9}, {%0,%1,%2,%3};"
        : "+f"(c[0]), "+f"(c[1]), "+f"(c[2]), "+f"(c[3])
        : "r"(a[0]), "r"(a[1]), "r"(a[2]), "r"(a[3]), "r"(b[0]), "r"(b[1]));
}

__device__ __forceinline__ void ldm_x4(unsigned& r0, unsigned& r1, unsigned& r2,
                                       unsigned& r3, unsigned addr) {
    asm volatile("ldmatrix.sync.aligned.m8n8.x4.shared.b16 {%0,%1,%2,%3}, [%4];"
                 : "=r"(r0), "=r"(r1), "=r"(r2), "=r"(r3) : "r"(addr));
}

// ======================= histogram (separate so CSR chain can start early) =======================

__global__ void k_hist(const int* __restrict__ dst) {
    int e = blockIdx.x * blockDim.x + threadIdx.x;
    if (e < NE) atomicAdd(&g_deg[dst[e]], 1);
}

// ======================= splits prep: x split + W splits (independent of CSR) =======================

__global__ void k_prep_splits(const float* __restrict__ x, const float* __restrict__ W1,
                              const float* __restrict__ W2, const float* __restrict__ W3) {
    const int NX = NN * 32;                    // float4 count of x
    long i = (long)blockIdx.x * blockDim.x + threadIdx.x;
    if (i < NX) {
        float4 v = ((const float4*)x)[i];
        __half h0, h1, h2, h3, l0, l1, l2, l3;
        splith(v.x, h0, l0); splith(v.y, h1, l1);
        splith(v.z, h2, l2); splith(v.w, h3, l3);
        ((__half2*)g_xh)[2 * i]     = __halves2half2(h0, h1);
        ((__half2*)g_xh)[2 * i + 1] = __halves2half2(h2, h3);
        ((__half2*)g_xl)[2 * i]     = __halves2half2(l0, l1);
        ((__half2*)g_xl)[2 * i + 1] = __halves2half2(l2, l3);
        return;
    }
    i -= NX;
    if (i < 256 * 256) {                       // W1 full split
        __half h, l; splith(W1[i], h, l);
        g_W1h[i] = h; g_W1l[i] = l;
        return;
    }
    i -= 256 * 256;
    if (i < 256 * 512) {                       // W2 full split
        __half h, l; splith(W2[i], h, l);
        g_W2h[i] = h; g_W2l[i] = l;
        return;
    }
    i -= 256 * 512;
    if (i < 128 * 256) {                       // W3 stacked [self; neigh]
        int r = (int)(i >> 8), c = (int)(i & 255);
        float v = (r < 64) ? W3[r * 512 + c] : W3[(r - 64) * 512 + 256 + c];
        __half h, l; splith(v, h, l);
        g_W3h[i] = h; g_W3l[i] = l;
    }
}

#define SPLITS_TOTAL (NN * 32 + 256 * 256 + 256 * 512 + 128 * 256)

// ======================= CSR mid: scan + fill (+ re-zero deg for next launch) =======================

#define MIDT 1024
#define CH2 ((NN + MIDT - 1) / MIDT)   // 98

__global__ void __launch_bounds__(MIDT)
k_csr_mid() {
    __shared__ int sp[MIDT];
    int t = threadIdx.x;
    int base = t * CH2;
    int end = base + CH2; if (end > NN) end = NN;

    int s = 0;
    for (int i = base; i < end; i++) s += g_deg[i];
    sp[t] = s;
    __syncthreads();

#pragma unroll
    for (int off = 1; off < MIDT; off <<= 1) {
        int v = (t >= off) ? sp[t - off] : 0;
        __syncthreads();
        sp[t] += v;
        __syncthreads();
    }
    int run = sp[t] - s;                       // exclusive prefix
    if (t == MIDT - 1) g_rowptr[NN] = sp[MIDT - 1];

    for (int i = base; i < end; i++) {
        g_rowptr[i] = run;
        g_cursor[i] = run;
        run += g_deg[i];
        g_deg[i] = 0;                          // invariant for next launch
    }
}

__global__ void k_scatter(const int* __restrict__ src, const int* __restrict__ dst) {
    int e = blockIdx.x * blockDim.x + threadIdx.x;
    if (e < NE) {
        int p = atomicAdd(&g_cursor[dst[e]], 1);
        g_csr[p] = src[e];
    }
}

// ======================= aggregation from fp32 source (layer 1) =======================

template <int DV, int UNR>
__global__ void k_agg(const float* __restrict__ h, __half* __restrict__ oh,
                      __half* __restrict__ ol) {
    int gwarp = (blockIdx.x * blockDim.x + threadIdx.x) >> 5;
    int lane = threadIdx.x & 31;
    if (gwarp >= NN) return;

    int s0 = g_rowptr[gwarp];
    int s1 = g_rowptr[gwarp + 1];

    float4 acc[DV];
#pragma unroll
    for (int j = 0; j < DV; j++) acc[j] = make_float4(0.f, 0.f, 0.f, 0.f);

    const int stride4 = DV * 32;
    const float4* __restrict__ hv = (const float4*)h;

    int e = s0;
    for (; e + UNR <= s1; e += UNR) {
        float4 v[UNR][DV];
#pragma unroll
        for (int u = 0; u < UNR; u++) {
            const float4* r = hv + (long)g_csr[e + u] * stride4;
#pragma unroll
            for (int j = 0; j < DV; j++) v[u][j] = r[lane + 32 * j];
        }
#pragma unroll
        for (int u = 0; u < UNR; u++)
#pragma unroll
            for (int j = 0; j < DV; j++) {
                acc[j].x += v[u][j].x; acc[j].y += v[u][j].y;
                acc[j].z += v[u][j].z; acc[j].w += v[u][j].w;
            }
    }
    for (; e < s1; e++) {
        const float4* r = hv + (long)g_csr[e] * stride4;
#pragma unroll
        for (int j = 0; j < DV; j++) {
            float4 v = r[lane + 32 * j];
            acc[j].x += v.x; acc[j].y += v.y; acc[j].z += v.z; acc[j].w += v.w;
        }
    }

    int deg = s1 - s0;
    float inv = 1.0f / (float)(deg > 0 ? deg : 1);
    __half2* ovh = (__half2*)oh + (long)gwarp * (stride4 * 2);
    __half2* ovl = (__half2*)ol + (long)gwarp * (stride4 * 2);
#pragma unroll
    for (int j = 0; j < DV; j++) {
        float4 v;
        v.x = acc[j].x * inv; v.y = acc[j].y * inv;
        v.z = acc[j].z * inv; v.w = acc[j].w * inv;
        __half h0, h1, h2, h3, l0, l1, l2, l3;
        splith(v.x, h0, l0); splith(v.y, h1, l1);
        splith(v.z, h2, l2); splith(v.w, h3, l3);
        int f = lane + 32 * j;
        ovh[2 * f]     = __halves2half2(h0, h1);
        ovh[2 * f + 1] = __halves2half2(h2, h3);
        ovl[2 * f]     = __halves2half2(l0, l1);
        ovl[2 * f + 1] = __halves2half2(l2, l3);
    }
}

// ======================= aggregation from hi/lo fp16 planes (layer 2, 256-dim) =======================

__device__ __forceinline__ void acc8(float* a, uint4 h, uint4 l) {
    const unsigned* hp = (const unsigned*)&h;
    const unsigned* lp = (const unsigned*)&l;
#pragma unroll
    for (int q = 0; q < 4; q++) {
        float2 fh = __half22float2(*(const __half2*)&hp[q]);
        float2 fl = __half22float2(*(const __half2*)&lp[q]);
        a[2 * q]     += fh.x + fl.x;
        a[2 * q + 1] += fh.y + fl.y;
    }
}

__global__ void k_agg_hl(const __half* __restrict__ hi, const __half* __restrict__ lo,
                         __half* __restrict__ oh, __half* __restrict__ ol) {
    int gwarp = (blockIdx.x * blockDim.x + threadIdx.x) >> 5;
    int lane = threadIdx.x & 31;
    if (gwarp >= NN) return;

    int s0 = g_rowptr[gwarp];
    int s1 = g_rowptr[gwarp + 1];

    float acc[8];
#pragma unroll
    for (int q = 0; q < 8; q++) acc[q] = 0.f;

    const uint4* hv = (const uint4*)hi;        // 32 uint4 per 256-half row
    const uint4* lv = (const uint4*)lo;

    int e = s0;
    for (; e + 4 <= s1; e += 4) {
        uint4 h0v, l0v, h1v, l1v, h2v, l2v, h3v, l3v;
        {
            long r0 = (long)g_csr[e] * 32,     r1 = (long)g_csr[e + 1] * 32;
            long r2 = (long)g_csr[e + 2] * 32, r3 = (long)g_csr[e + 3] * 32;
            h0v = hv[r0 + lane]; l0v = lv[r0 + lane];
            h1v = hv[r1 + lane]; l1v = lv[r1 + lane];
            h2v = hv[r2 + lane]; l2v = lv[r2 + lane];
            h3v = hv[r3 + lane]; l3v = lv[r3 + lane];
        }
        acc8(acc, h0v, l0v);
        acc8(acc, h1v, l1v);
        acc8(acc, h2v, l2v);
        acc8(acc, h3v, l3v);
    }
    for (; e < s1; e++) {
        long ra = (long)g_csr[e] * 32;
        acc8(acc, hv[ra + lane], lv[ra + lane]);
    }

    int deg = s1 - s0;
    float inv = 1.0f / (float)(deg > 0 ? deg : 1);
    __half2* ovh = (__half2*)oh + (long)gwarp * 128 + lane * 4;
    __half2* ovl = (__half2*)ol + (long)gwarp * 128 + lane * 4;
#pragma unroll
    for (int q = 0; q < 4; q++) {
        float v0 = acc[2 * q] * inv, v1 = acc[2 * q + 1] * inv;
        __half h0, h1, l0, l1;
        splith(v0, h0, l0); splith(v1, h1, l1);
        ovh[q] = __halves2half2(h0, h1);
        ovl[q] = __halves2half2(l0, l1);
    }
}

// ======================= fp16 3-product concat-GEMM (round-10 body + wait fix) =======================
// C[M, N_OUT] = [A1 | A2] @ W^T (+ bias, optional ReLU), as hi.hi + hi.lo + lo.hi.
// OMODE: 0 = fp32 Cf only, 2 = fp16 splits only.
// Final iteration MUST wait_group 0 (wait_group 1 leaves the last chunk in flight).

template <int N_OUT, int K, bool CONCAT, bool RELU, int OMODE, bool HAS_BIAS>
__global__ void __launch_bounds__(256, 2)
k_mma(const __half* __restrict__ A1h, const __half* __restrict__ A2h,
      const __half* __restrict__ A1l, const __half* __restrict__ A2l,
      const __half* __restrict__ Wh,  const __half* __restrict__ Wl,
      const float* __restrict__ bias,
      float* __restrict__ Cf, __half* __restrict__ Ch, __half* __restrict__ Cl) {
    constexpr int D = CONCAT ? K / 2 : K;
    constexpr int NCP = K / 64;
    constexpr int NC3 = 3 * NCP;
    constexpr int NT = 8;
    constexpr int SH = 72;
    constexpr int A_BYTES = 128 * SH * 2;      // 18432
    constexpr int STAGE_B = 2 * A_BYTES;

    extern __shared__ char smem_raw[];
    const unsigned sbase = smem_u32(smem_raw);
    const int tid = threadIdx.x;
    const int wid = tid >> 5;
    const int lane = tid & 31;
    const int wm = wid & 3;
    const int wn = wid >> 2;
    const int n0 = blockIdx.x * 128;
    const int m0 = blockIdx.y * 128;

    const int lr = lane >> 2;
    const int lc = lane & 3;

    unsigned offA[2], offB[4];
#pragma unroll
    for (int mt = 0; mt < 2; mt++) {
        int row = wm * 32 + mt * 16 + (lane & 15);
        int col = (lane >> 4) * 8;
        offA[mt] = (unsigned)(row * SH + col) * 2;
    }
#pragma unroll
    for (int p = 0; p < 4; p++) {
        int row = wn * 64 + p * 16 + (lane & 7) + ((lane >> 4) & 1) * 8;
        int col = ((lane >> 3) & 1) * 8;
        offB[p] = (unsigned)(A_BYTES) + (unsigned)(row * SH + col) * 2;
    }

    float acc[2][NT][4];
#pragma unroll
    for (int mt = 0; mt < 2; mt++)
#pragma unroll
        for (int nt = 0; nt < NT; nt++)
#pragma unroll
            for (int q = 0; q < 4; q++) acc[mt][nt][q] = 0.f;

    auto load_chunk = [&](int j, int s) {
        unsigned base = sbase + s * STAGE_B;
        int p = j / NCP;                       // 0: hi.hi, 1: hi.lo, 2: lo.hi
        int k0 = (j - p * NCP) * 64;
        const __half* A;
        int ka;
        if (CONCAT && k0 >= D) {
            A = (p < 2) ? A2h : A2l; ka = k0 - D;
        } else {
            A = (p < 2) ? A1h : A1l; ka = k0;
        }
        const __half* B = (p == 1) ? Wl : Wh;
#pragma unroll
        for (int q = 0; q < 4; q++) {
            int idx = tid + 256 * q;
            int row = idx >> 3, c8 = idx & 7;
            cp16(base + (unsigned)(row * (SH * 2) + c8 * 16),
                 A + (long)(m0 + row) * D + ka + c8 * 8);
        }
#pragma unroll
        for (int q = 0; q < 4; q++) {
            int idx = tid + 256 * q;
            int n = idx >> 3, c8 = idx & 7;
            cp16(base + (unsigned)(A_BYTES + n * (SH * 2) + c8 * 16),
                 B + (long)(n0 + n) * K + k0 + c8 * 8);
        }
        CP_COMMIT();
    };

    load_chunk(0, 0);
    load_chunk(1, 1);

#pragma unroll 1
    for (int i = 0; i < NC3; i++) {
        int s = i & 1;
        if (i == NC3 - 1) { CP_WAIT0(); } else { CP_WAIT1(); }
        __syncthreads();

        unsigned stage = sbase + s * STAGE_B;

#pragma unroll
        for (int ks = 0; ks < 4; ks++) {
            unsigned kso = ks * 32;
            unsigned a[2][4];
#pragma unroll
            for (int mt = 0; mt < 2; mt++)
                ldm_x4(a[mt][0], a[mt][1], a[mt][2], a[mt][3],
                       stage + offA[mt] + kso);
            unsigned b[NT][2];
#pragma unroll
            for (int p = 0; p < 4; p++)
                ldm_x4(b[2 * p][0], b[2 * p][1], b[2 * p + 1][0], b[2 * p + 1][1],
                       stage + offB[p] + kso);
#pragma unroll
            for (int mt = 0; mt < 2; mt++)
#pragma unroll
                for (int nt = 0; nt < NT; nt++)
                    mma16(acc[mt][nt], a[mt], b[nt]);
        }

        __syncthreads();
        if (i + 2 < NC3) load_chunk(i + 2, s);
    }

    // epilogue
#pragma unroll
    for (int mt = 0; mt < 2; mt++) {
#pragma unroll
        for (int nt = 0; nt < NT; nt++) {
            int n = n0 + wn * 64 + nt * 8 + lc * 2;
            float b0 = 0.f, b1 = 0.f;
            if (HAS_BIAS) { b0 = bias[n]; b1 = bias[n + 1]; }
            int r0 = m0 + wm * 32 + mt * 16 + lr;
#pragma unroll
            for (int h = 0; h < 2; h++) {
                int r = r0 + h * 8;
                if (r < NN) {
                    long off = (long)r * N_OUT + n;
                    float v0 = acc[mt][nt][2 * h + 0] + b0;
                    float v1 = acc[mt][nt][2 * h + 1] + b1;
                    if (RELU) { v0 = v0 > 0.f ? v0 : 0.f; v1 = v1 > 0.f ? v1 : 0.f; }
                    if (OMODE == 0) {
                        *(float2*)(Cf + off) = make_float2(v0, v1);
                    } else {
                        __half h0, h1, l0, l1;
                        splith(v0, h0, l0); splith(v1, h1, l1);
                        ((__half2*)Ch)[off >> 1] = __halves2half2(h0, h1);
                        ((__half2*)Cl)[off >> 1] = __halves2half2(l0, l1);
                    }
                }
            }
        }
    }
}

// ======================= layer-3 final: out = z_self + mean(z_neigh) + b =======================

__global__ void k_agg_out(const float* __restrict__ z, const float* __restrict__ b3,
                          float* __restrict__ out) {
    int gwarp = (blockIdx.x * blockDim.x + threadIdx.x) >> 5;
    int lane = threadIdx.x & 31;
    if (gwarp >= NN) return;

    int s0 = g_rowptr[gwarp];
    int s1 = g_rowptr[gwarp + 1];

    float2 acc = make_float2(0.f, 0.f);
    const float2* zn = (const float2*)(z + 64);
    int e = s0;
    for (; e + 3 < s1; e += 4) {
        float2 v0 = zn[(long)g_csr[e] * 64 + lane];
        float2 v1 = zn[(long)g_csr[e + 1] * 64 + lane];
        float2 v2 = zn[(long)g_csr[e + 2] * 64 + lane];
        float2 v3 = zn[(long)g_csr[e + 3] * 64 + lane];
        acc.x += (v0.x + v1.x) + (v2.x + v3.x);
        acc.y += (v0.y + v1.y) + (v2.y + v3.y);
    }
    for (; e < s1; e++) {
        float2 v = zn[(long)g_csr[e] * 64 + lane];
        acc.x += v.x; acc.y += v.y;
    }
    int deg = s1 - s0;
    float inv = 1.0f / (float)(deg > 0 ? deg : 1);

    float2 self = ((const float2*)z)[(long)gwarp * 64 + lane];
    float2 bb = ((const float2*)b3)[lane];
    float2 r;
    r.x = self.x + acc.x * inv + bb.x;
    r.y = self.y + acc.y * inv + bb.y;
    ((float2*)out)[(long)gwarp * 32 + lane] = r;
}

// ======================= launch =======================

extern "C" void kernel_launch(void* const* d_in, const int* in_sizes, int n_in,
                              void* d_out, int out_size) {
    const float* x   = (const float*)d_in[0];
    const int*   src = (const int*)d_in[1];
    const int*   dst = (const int*)d_in[2];
    const float* W1  = (const float*)d_in[3];
    const float* b1  = (const float*)d_in[4];
    const float* W2  = (const float*)d_in[5];
    const float* b2  = (const float*)d_in[6];
    const float* W3  = (const float*)d_in[7];
    const float* b3  = (const float*)d_in[8];
    float* out = (float*)d_out;

    __half *xh, *xl, *hNh, *hNl, *hAh, *hAl, *hBh, *hBl;
    __half *W1h, *W1l, *W2h, *W2l, *W3h, *W3l;
    float *z;
    cudaGetSymbolAddress((void**)&xh, g_xh);
    cudaGetSymbolAddress((void**)&xl, g_xl);
    cudaGetSymbolAddress((void**)&hNh, g_hNh);
    cudaGetSymbolAddress((void**)&hNl, g_hNl);
    cudaGetSymbolAddress((void**)&hAh, g_hAh);
    cudaGetSymbolAddress((void**)&hAl, g_hAl);
    cudaGetSymbolAddress((void**)&hBh, g_hBh);
    cudaGetSymbolAddress((void**)&hBl, g_hBl);
    cudaGetSymbolAddress((void**)&z, g_z);
    cudaGetSymbolAddress((void**)&W1h, g_W1h);
    cudaGetSymbolAddress((void**)&W1l, g_W1l);
    cudaGetSymbolAddress((void**)&W2h, g_W2h);
    cudaGetSymbolAddress((void**)&W2l, g_W2l);
    cudaGetSymbolAddress((void**)&W3h, g_W3h);
    cudaGetSymbolAddress((void**)&W3l, g_W3l);

    constexpr int SMB = 2 * 2 * 128 * 72 * 2;   // 73728
    cudaFuncSetAttribute(k_mma<256, 256, true,  true,  2, true>,
                         cudaFuncAttributeMaxDynamicSharedMemorySize, SMB);
    cudaFuncSetAttribute(k_mma<256, 512, true,  true,  2, true>,
                         cudaFuncAttributeMaxDynamicSharedMemorySize, SMB);
    cudaFuncSetAttribute(k_mma<128, 256, false, false, 0, false>,
                         cudaFuncAttributeMaxDynamicSharedMemorySize, SMB);

    const int AGG_BLOCKS = (NN + 7) / 8;
    const int GM = NNP / 128;   // 782

    // --- fork: x/W splits on s2 (independent of CSR chain) ---
    cudaEventRecord(g_ev0, 0);
    cudaStreamWaitEvent(g_s2, g_ev0, 0);
    k_prep_splits<<<(SPLITS_TOTAL + 255) / 256, 256, 0, g_s2>>>(x, W1, W2, W3);

    // --- main stream: CSR build + L1 aggregation (reads fp32 x directly) ---
    k_hist<<<(NE + 255) / 256, 256>>>(dst);
    k_csr_mid<<<1, MIDT>>>();
    k_scatter<<<(NE + 255) / 256, 256>>>(src, dst);
    k_agg<1, 4><<<AGG_BLOCKS, 256>>>(x, hNh, hNl);

    // --- join: L1 GEMM needs xh/xl + W1 splits + hN ---
    cudaEventRecord(g_ev1, g_s2);
    cudaStreamWaitEvent(0, g_ev1, 0);

    // ---- layer 1: [x | agg(x)] (K=256) -> 256, ReLU; splits only ----
    k_mma<256, 256, true, true, 2, true><<<dim3(2, GM), 256, SMB>>>(
        xh, hNh, xl, hNl, W1h, W1l, b1, nullptr, hAh, hAl);

    // ---- layer 2: [hA | agg(hA)] (K=512) -> 256, ReLU; agg reads hi/lo planes ----
    k_agg_hl<<<AGG_BLOCKS, 256>>>(hAh, hAl, hNh, hNl);
    k_mma<256, 512, true, true, 2, true><<<dim3(2, GM), 256, SMB>>>(
        hAh, hNh, hAl, hNl, W2h, W2l, b2, nullptr, hBh, hBl);

    // ---- layer 3 (linear-reordered): z = hB @ [W3_self; W3_neigh]^T, then combine ----
    k_mma<128, 256, false, false, 0, false><<<dim3(1, GM), 256, SMB>>>(
        hBh, hBh, hBl, hBl, W3h, W3l, nullptr, z, nullptr, nullptr);
    k_agg_out<<<AGG_BLOCKS, 256>>>(z, b3, out);
}

// round 15
// speedup vs baseline: 1.1474x; 1.0028x over previous
#include <cuda_runtime.h>
#include <cuda_fp16.h>

#define NN 100000
#define NNP 100096            // padded to multiple of 128 (782 * 128)
#define NE 1600000

// ---- scratch (static device globals; zero-initialized; no allocation allowed) ----
__device__ __half g_xh[NNP * 128];      // x hi/lo (fp16 split, padded)
__device__ __half g_xl[NNP * 128];
__device__ __half g_hNh[NNP * 256];     // aggregated neighbor feats hi/lo
__device__ __half g_hNl[NNP * 256];
__device__ __half g_hAh[NNP * 256];     // layer-1 output hi/lo
__device__ __half g_hAl[NNP * 256];
__device__ __half g_hBh[NNP * 256];     // layer-2 output hi/lo
__device__ __half g_hBl[NNP * 256];
__device__ float  g_z[NNP * 128];       // layer-3 GEMM out: [z_self | z_neigh]
__device__ __half g_W1h[256 * 256];
__device__ __half g_W1l[256 * 256];
__device__ __half g_W2h[256 * 512];
__device__ __half g_W2l[256 * 512];
__device__ __half g_W3h[128 * 256];     // stacked [W3_self; W3_neigh]
__device__ __half g_W3l[128 * 256];
__device__ int   g_deg[NN];             // zero at launch entry (static init +
                                        // re-zeroed by k_csr_mid each launch)
__device__ int   g_rowptr[NN + 1];
__device__ int   g_cursor[NN];
__device__ int   g_csr[NE];

// ======================= helpers =======================

__device__ __forceinline__ void splith(float v, __half& h, __half& l) {
    h = __float2half_rn(v);
    l = __float2half_rn(v - __half2float(h));
}

__device__ __forceinline__ unsigned smem_u32(const void* p) {
    unsigned a;
    asm("{ .reg .u64 t; cvta.to.shared.u64 t, %1; cvt.u32.u64 %0, t; }" : "=r"(a) : "l"(p));
    return a;
}

__device__ __forceinline__ void cp16(unsigned dst, const void* src) {
    asm volatile("cp.async.cg.shared.global [%0], [%1], 16;" :: "r"(dst), "l"(src));
}
#define CP_COMMIT() asm volatile("cp.async.commit_group;" ::: "memory")
#define CP_WAIT1()  asm volatile("cp.async.wait_group 1;" ::: "memory")
#define CP_WAIT0()  asm volatile("cp.async.wait_group 0;" ::: "memory")

__device__ __forceinline__ void mma16(float* c, const unsigned* a, const unsigned* b) {
    asm volatile(
        "mma.sync.aligned.m16n8k16.row.col.f32.f16.f16.f32 "
        "{%0,%1,%2,%3}, {%4,%5,%6,%7}, {%8,%9}, {%0,%1,%2,%3};"
        : "+f"(c[0]), "+f"(c[1]), "+f"(c[2]), "+f"(c[3])
        : "r"(a[0]), "r"(a[1]), "r"(a[2]), "r"(a[3]), "r"(b[0]), "r"(b[1]));
}

__device__ __forceinline__ void ldm_x4(unsigned& r0, unsigned& r1, unsigned& r2,
                                       unsigned& r3, unsigned addr) {
    asm volatile("ldmatrix.sync.aligned.m8n8.x4.shared.b16 {%0,%1,%2,%3}, [%4];"
                 : "=r"(r0), "=r"(r1), "=r"(r2), "=r"(r3) : "r"(addr));
}

// ======================= fused prep: x split, W splits, dst histogram =======================
// g_deg is zero on entry (static init on first launch; re-zeroed by k_csr_mid after).

__global__ void k_prep(const float* __restrict__ x, const float* __restrict__ W1,
                       const float* __restrict__ W2, const float* __restrict__ W3,
                       const int* __restrict__ dst) {
    const int NX = NN * 32;                    // float4 count of x
    long i = (long)blockIdx.x * blockDim.x + threadIdx.x;
    if (i < NX) {
        float4 v = ((const float4*)x)[i];
        __half h0, h1, h2, h3, l0, l1, l2, l3;
        splith(v.x, h0, l0); splith(v.y, h1, l1);
        splith(v.z, h2, l2); splith(v.w, h3, l3);
        ((__half2*)g_xh)[2 * i]     = __halves2half2(h0, h1);
        ((__half2*)g_xh)[2 * i + 1] = __halves2half2(h2, h3);
        ((__half2*)g_xl)[2 * i]     = __halves2half2(l0, l1);
        ((__half2*)g_xl)[2 * i + 1] = __halves2half2(l2, l3);
        return;
    }
    i -= NX;
    if (i < 256 * 256) {                       // W1 full split
        __half h, l; splith(W1[i], h, l);
        g_W1h[i] = h; g_W1l[i] = l;
        return;
    }
    i -= 256 * 256;
    if (i < 256 * 512) {                       // W2 full split
        __half h, l; splith(W2[i], h, l);
        g_W2h[i] = h; g_W2l[i] = l;
        return;
    }
    i -= 256 * 512;
    if (i < 128 * 256) {                       // W3 stacked [self; neigh]
        int r = (int)(i >> 8), c = (int)(i & 255);
        float v = (r < 64) ? W3[r * 512 + c] : W3[(r - 64) * 512 + 256 + c];
        __half h, l; splith(v, h, l);
        g_W3h[i] = h; g_W3l[i] = l;
        return;
    }
    i -= 128 * 256;
    if (i < NE) atomicAdd(&g_deg[dst[i]], 1);  // histogram (overlaps with splits)
}

#define PREP_TOTAL (NN * 32 + 256 * 256 + 256 * 512 + 128 * 256 + NE)

// ======================= CSR mid: scan + fill (+ re-zero deg for next launch) =======================

#define MIDT 1024
#define CH2 ((NN + MIDT - 1) / MIDT)   // 98

__global__ void __launch_bounds__(MIDT)
k_csr_mid() {
    __shared__ int sp[MIDT];
    int t = threadIdx.x;
    int base = t * CH2;
    int end = base + CH2; if (end > NN) end = NN;

    int s = 0;
    for (int i = base; i < end; i++) s += g_deg[i];
    sp[t] = s;
    __syncthreads();

#pragma unroll
    for (int off = 1; off < MIDT; off <<= 1) {
        int v = (t >= off) ? sp[t - off] : 0;
        __syncthreads();
        sp[t] += v;
        __syncthreads();
    }
    int run = sp[t] - s;                       // exclusive prefix
    if (t == MIDT - 1) g_rowptr[NN] = sp[MIDT - 1];

    for (int i = base; i < end; i++) {
        g_rowptr[i] = run;
        g_cursor[i] = run;
        run += g_deg[i];
        g_deg[i] = 0;                          // invariant for next launch
    }
}

__global__ void k_scatter(const int* __restrict__ src, const int* __restrict__ dst) {
    int e = blockIdx.x * blockDim.x + threadIdx.x;
    if (e < NE) {
        int p = atomicAdd(&g_cursor[dst[e]], 1);
        g_csr[p] = src[e];
    }
}

// ======================= aggregation from fp32 source (layer 1) =======================

template <int DV, int UNR>
__global__ void k_agg(const float* __restrict__ h, __half* __restrict__ oh,
                      __half* __restrict__ ol) {
    int gwarp = (blockIdx.x * blockDim.x + threadIdx.x) >> 5;
    int lane = threadIdx.x & 31;
    if (gwarp >= NN) return;

    int s0 = g_rowptr[gwarp];
    int s1 = g_rowptr[gwarp + 1];

    float4 acc[DV];
#pragma unroll
    for (int j = 0; j < DV; j++) acc[j] = make_float4(0.f, 0.f, 0.f, 0.f);

    const int stride4 = DV * 32;
    const float4* __restrict__ hv = (const float4*)h;

    int e = s0;
    for (; e + UNR <= s1; e += UNR) {
        float4 v[UNR][DV];
#pragma unroll
        for (int u = 0; u < UNR; u++) {
            const float4* r = hv + (long)g_csr[e + u] * stride4;
#pragma unroll
            for (int j = 0; j < DV; j++) v[u][j] = r[lane + 32 * j];
        }
#pragma unroll
        for (int u = 0; u < UNR; u++)
#pragma unroll
            for (int j = 0; j < DV; j++) {
                acc[j].x += v[u][j].x; acc[j].y += v[u][j].y;
                acc[j].z += v[u][j].z; acc[j].w += v[u][j].w;
            }
    }
    for (; e < s1; e++) {
        const float4* r = hv + (long)g_csr[e] * stride4;
#pragma unroll
        for (int j = 0; j < DV; j++) {
            float4 v = r[lane + 32 * j];
            acc[j].x += v.x; acc[j].y += v.y; acc[j].z += v.z; acc[j].w += v.w;
        }
    }

    int deg = s1 - s0;
    float inv = 1.0f / (float)(deg > 0 ? deg : 1);
    __half2* ovh = (__half2*)oh + (long)gwarp * (stride4 * 2);
    __half2* ovl = (__half2*)ol + (long)gwarp * (stride4 * 2);
#pragma unroll
    for (int j = 0; j < DV; j++) {
        float4 v;
        v.x = acc[j].x * inv; v.y = acc[j].y * inv;
        v.z = acc[j].z * inv; v.w = acc[j].w * inv;
        __half h0, h1, h2, h3, l0, l1, l2, l3;
        splith(v.x, h0, l0); splith(v.y, h1, l1);
        splith(v.z, h2, l2); splith(v.w, h3, l3);
        int f = lane + 32 * j;
        ovh[2 * f]     = __halves2half2(h0, h1);
        ovh[2 * f + 1] = __halves2half2(h2, h3);
        ovl[2 * f]     = __halves2half2(l0, l1);
        ovl[2 * f + 1] = __halves2half2(l2, l3);
    }
}

// ======================= aggregation from hi/lo fp16 planes (layer 2, 256-dim) =======================
// Reconstructs v = hi + lo per element (error ~2^-22). One warp/node; lane covers 8 elems.

__device__ __forceinline__ void acc8(float* a, uint4 h, uint4 l) {
    const unsigned* hp = (const unsigned*)&h;
    const unsigned* lp = (const unsigned*)&l;
#pragma unroll
    for (int q = 0; q < 4; q++) {
        float2 fh = __half22float2(*(const __half2*)&hp[q]);
        float2 fl = __half22float2(*(const __half2*)&lp[q]);
        a[2 * q]     += fh.x + fl.x;
        a[2 * q + 1] += fh.y + fl.y;
    }
}

__global__ void k_agg_hl(const __half* __restrict__ hi, const __half* __restrict__ lo,
                         __half* __restrict__ oh, __half* __restrict__ ol) {
    int gwarp = (blockIdx.x * blockDim.x + threadIdx.x) >> 5;
    int lane = threadIdx.x & 31;
    if (gwarp >= NN) return;

    int s0 = g_rowptr[gwarp];
    int s1 = g_rowptr[gwarp + 1];

    float acc[8];
#pragma unroll
    for (int q = 0; q < 8; q++) acc[q] = 0.f;

    const uint4* hv = (const uint4*)hi;        // 32 uint4 per 256-half row
    const uint4* lv = (const uint4*)lo;

    int e = s0;
    for (; e + 4 <= s1; e += 4) {
        uint4 h0v, l0v, h1v, l1v, h2v, l2v, h3v, l3v;
        {
            long r0 = (long)g_csr[e] * 32,     r1 = (long)g_csr[e + 1] * 32;
            long r2 = (long)g_csr[e + 2] * 32, r3 = (long)g_csr[e + 3] * 32;
            h0v = hv[r0 + lane]; l0v = lv[r0 + lane];
            h1v = hv[r1 + lane]; l1v = lv[r1 + lane];
            h2v = hv[r2 + lane]; l2v = lv[r2 + lane];
            h3v = hv[r3 + lane]; l3v = lv[r3 + lane];
        }
        acc8(acc, h0v, l0v);
        acc8(acc, h1v, l1v);
        acc8(acc, h2v, l2v);
        acc8(acc, h3v, l3v);
    }
    for (; e < s1; e++) {
        long ra = (long)g_csr[e] * 32;
        acc8(acc, hv[ra + lane], lv[ra + lane]);
    }

    int deg = s1 - s0;
    float inv = 1.0f / (float)(deg > 0 ? deg : 1);
    __half2* ovh = (__half2*)oh + (long)gwarp * 128 + lane * 4;
    __half2* ovl = (__half2*)ol + (long)gwarp * 128 + lane * 4;
#pragma unroll
    for (int q = 0; q < 4; q++) {
        float v0 = acc[2 * q] * inv, v1 = acc[2 * q + 1] * inv;
        __half h0, h1, l0, l1;
        splith(v0, h0, l0); splith(v1, h1, l1);
        ovh[q] = __halves2half2(h0, h1);
        ovl[q] = __halves2half2(l0, l1);
    }
}

// ======================= fp16 3-product concat-GEMM (2-stage; last-chunk wait fixed) =======================
// C[M, N_OUT] = [A1 | A2] @ W^T (+ bias, optional ReLU), as hi.hi + hi.lo + lo.hi.
// OMODE: 0 = fp32 Cf only, 2 = fp16 splits only.
// Final iteration MUST wait_group 0 — wait_group 1 leaves the last committed
// chunk potentially in flight (race confirmed under SM contention, round 12).

template <int N_OUT, int K, bool CONCAT, bool RELU, int OMODE, bool HAS_BIAS>
__global__ void __launch_bounds__(256, 2)
k_mma(const __half* __restrict__ A1h, const __half* __restrict__ A2h,
      const __half* __restrict__ A1l, const __half* __restrict__ A2l,
      const __half* __restrict__ Wh,  const __half* __restrict__ Wl,
      const float* __restrict__ bias,
      float* __restrict__ Cf, __half* __restrict__ Ch, __half* __restrict__ Cl) {
    constexpr int D = CONCAT ? K / 2 : K;
    constexpr int NCP = K / 64;
    constexpr int NC3 = 3 * NCP;
    constexpr int NT = 8;
    constexpr int SH = 72;
    constexpr int A_BYTES = 128 * SH * 2;      // 18432
    constexpr int STAGE_B = 2 * A_BYTES;

    extern __shared__ char smem_raw[];
    const unsigned sbase = smem_u32(smem_raw);
    const int tid = threadIdx.x;
    const int wid = tid >> 5;
    const int lane = tid & 31;
    const int wm = wid & 3;
    const int wn = wid >> 2;
    const int n0 = blockIdx.x * 128;
    const int m0 = blockIdx.y * 128;

    const int lr = lane >> 2;
    const int lc = lane & 3;

    unsigned offA[2], offB[4];
#pragma unroll
    for (int mt = 0; mt < 2; mt++) {
        int row = wm * 32 + mt * 16 + (lane & 15);
        int col = (lane >> 4) * 8;
        offA[mt] = (unsigned)(row * SH + col) * 2;
    }
#pragma unroll
    for (int p = 0; p < 4; p++) {
        int row = wn * 64 + p * 16 + (lane & 7) + ((lane >> 4) & 1) * 8;
        int col = ((lane >> 3) & 1) * 8;
        offB[p] = (unsigned)(A_BYTES) + (unsigned)(row * SH + col) * 2;
    }

    float acc[2][NT][4];
#pragma unroll
    for (int mt = 0; mt < 2; mt++)
#pragma unroll
        for (int nt = 0; nt < NT; nt++)
#pragma unroll
            for (int q = 0; q < 4; q++) acc[mt][nt][q] = 0.f;

    auto load_chunk = [&](int j, int s) {
        unsigned base = sbase + s * STAGE_B;
        int p = j / NCP;                       // 0: hi.hi, 1: hi.lo, 2: lo.hi
        int k0 = (j - p * NCP) * 64;
        const __half* A;
        int ka;
        if (CONCAT && k0 >= D) {
            A = (p < 2) ? A2h : A2l; ka = k0 - D;
        } else {
            A = (p < 2) ? A1h : A1l; ka = k0;
        }
        const __half* B = (p == 1) ? Wl : Wh;
#pragma unroll
        for (int q = 0; q < 4; q++) {
            int idx = tid + 256 * q;
            int row = idx >> 3, c8 = idx & 7;
            cp16(base + (unsigned)(row * (SH * 2) + c8 * 16),
                 A + (long)(m0 + row) * D + ka + c8 * 8);
        }
#pragma unroll
        for (int q = 0; q < 4; q++) {
            int idx = tid + 256 * q;
            int n = idx >> 3, c8 = idx & 7;
            cp16(base + (unsigned)(A_BYTES + n * (SH * 2) + c8 * 16),
                 B + (long)(n0 + n) * K + k0 + c8 * 8);
        }
        CP_COMMIT();
    };

    load_chunk(0, 0);
    load_chunk(1, 1);

#pragma unroll 1
    for (int i = 0; i < NC3; i++) {
        int s = i & 1;
        if (i == NC3 - 1) { CP_WAIT0(); } else { CP_WAIT1(); }
        __syncthreads();

        unsigned stage = sbase + s * STAGE_B;

#pragma unroll
        for (int ks = 0; ks < 4; ks++) {
            unsigned kso = ks * 32;
            unsigned a[2][4];
#pragma unroll
            for (int mt = 0; mt < 2; mt++)
                ldm_x4(a[mt][0], a[mt][1], a[mt][2], a[mt][3],
                       stage + offA[mt] + kso);
            unsigned b[NT][2];
#pragma unroll
            for (int p = 0; p < 4; p++)
                ldm_x4(b[2 * p][0], b[2 * p][1], b[2 * p + 1][0], b[2 * p + 1][1],
                       stage + offB[p] + kso);
#pragma unroll
            for (int mt = 0; mt < 2; mt++)
#pragma unroll
                for (int nt = 0; nt < NT; nt++)
                    mma16(acc[mt][nt], a[mt], b[nt]);
        }

        __syncthreads();
        if (i + 2 < NC3) load_chunk(i + 2, s);
    }

    // epilogue
#pragma unroll
    for (int mt = 0; mt < 2; mt++) {
#pragma unroll
        for (int nt = 0; nt < NT; nt++) {
            int n = n0 + wn * 64 + nt * 8 + lc * 2;
            float b0 = 0.f, b1 = 0.f;
            if (HAS_BIAS) { b0 = bias[n]; b1 = bias[n + 1]; }
            int r0 = m0 + wm * 32 + mt * 16 + lr;
#pragma unroll
            for (int h = 0; h < 2; h++) {
                int r = r0 + h * 8;
                if (r < NN) {
                    long off = (long)r * N_OUT + n;
                    float v0 = acc[mt][nt][2 * h + 0] + b0;
                    float v1 = acc[mt][nt][2 * h + 1] + b1;
                    if (RELU) { v0 = v0 > 0.f ? v0 : 0.f; v1 = v1 > 0.f ? v1 : 0.f; }
                    if (OMODE == 0) {
                        *(float2*)(Cf + off) = make_float2(v0, v1);
                    } else {
                        __half h0, h1, l0, l1;
                        splith(v0, h0, l0); splith(v1, h1, l1);
                        ((__half2*)Ch)[off >> 1] = __halves2half2(h0, h1);
                        ((__half2*)Cl)[off >> 1] = __halves2half2(l0, l1);
                    }
                }
            }
        }
    }
}

// ======================= layer-3 final: out = z_self + mean(z_neigh) + b =======================

__global__ void k_agg_out(const float* __restrict__ z, const float* __restrict__ b3,
                          float* __restrict__ out) {
    int gwarp = (blockIdx.x * blockDim.x + threadIdx.x) >> 5;
    int lane = threadIdx.x & 31;
    if (gwarp >= NN) return;

    int s0 = g_rowptr[gwarp];
    int s1 = g_rowptr[gwarp + 1];

    float2 acc = make_float2(0.f, 0.f);
    const float2* zn = (const float2*)(z + 64);
    int e = s0;
    for (; e + 3 < s1; e += 4) {
        float2 v0 = zn[(long)g_csr[e] * 64 + lane];
        float2 v1 = zn[(long)g_csr[e + 1] * 64 + lane];
        float2 v2 = zn[(long)g_csr[e + 2] * 64 + lane];
        float2 v3 = zn[(long)g_csr[e + 3] * 64 + lane];
        acc.x += (v0.x + v1.x) + (v2.x + v3.x);
        acc.y += (v0.y + v1.y) + (v2.y + v3.y);
    }
    for (; e < s1; e++) {
        float2 v = zn[(long)g_csr[e] * 64 + lane];
        acc.x += v.x; acc.y += v.y;
    }
    int deg = s1 - s0;
    float inv = 1.0f / (float)(deg > 0 ? deg : 1);

    float2 self = ((const float2*)z)[(long)gwarp * 64 + lane];
    float2 bb = ((const float2*)b3)[lane];
    float2 r;
    r.x = self.x + acc.x * inv + bb.x;
    r.y = self.y + acc.y * inv + bb.y;
    ((float2*)out)[(long)gwarp * 32 + lane] = r;
}

// ======================= launch =======================

extern "C" void kernel_launch(void* const* d_in, const int* in_sizes, int n_in,
                              void* d_out, int out_size) {
    const float* x   = (const float*)d_in[0];
    const int*   src = (const int*)d_in[1];
    const int*   dst = (const int*)d_in[2];
    const float* W1  = (const float*)d_in[3];
    const float* b1  = (const float*)d_in[4];
    const float* W2  = (const float*)d_in[5];
    const float* b2  = (const float*)d_in[6];
    const float* W3  = (const float*)d_in[7];
    const float* b3  = (const float*)d_in[8];
    float* out = (float*)d_out;

    __half *xh, *xl, *hNh, *hNl, *hAh, *hAl, *hBh, *hBl;
    __half *W1h, *W1l, *W2h, *W2l, *W3h, *W3l;
    float *z;
    cudaGetSymbolAddress((void**)&xh, g_xh);
    cudaGetSymbolAddress((void**)&xl, g_xl);
    cudaGetSymbolAddress((void**)&hNh, g_hNh);
    cudaGetSymbolAddress((void**)&hNl, g_hNl);
    cudaGetSymbolAddress((void**)&hAh, g_hAh);
    cudaGetSymbolAddress((void**)&hAl, g_hAl);
    cudaGetSymbolAddress((void**)&hBh, g_hBh);
    cudaGetSymbolAddress((void**)&hBl, g_hBl);
    cudaGetSymbolAddress((void**)&z, g_z);
    cudaGetSymbolAddress((void**)&W1h, g_W1h);
    cudaGetSymbolAddress((void**)&W1l, g_W1l);
    cudaGetSymbolAddress((void**)&W2h, g_W2h);
    cudaGetSymbolAddress((void**)&W2l, g_W2l);
    cudaGetSymbolAddress((void**)&W3h, g_W3h);
    cudaGetSymbolAddress((void**)&W3l, g_W3l);

    constexpr int SMB = 2 * 2 * 128 * 72 * 2;   // 73728
    cudaFuncSetAttribute(k_mma<256, 256, true,  true,  2, true>,
                         cudaFuncAttributeMaxDynamicSharedMemorySize, SMB);
    cudaFuncSetAttribute(k_mma<256, 512, true,  true,  2, true>,
                         cudaFuncAttributeMaxDynamicSharedMemorySize, SMB);
    cudaFuncSetAttribute(k_mma<128, 256, false, false, 0, false>,
                         cudaFuncAttributeMaxDynamicSharedMemorySize, SMB);

    // --- fused prep (splits + histogram) + CSR build, all serial (proven fastest) ---
    k_prep<<<(PREP_TOTAL + 255) / 256, 256>>>(x, W1, W2, W3, dst);
    k_csr_mid<<<1, MIDT>>>();
    k_scatter<<<(NE + 255) / 256, 256>>>(src, dst);

    const int AGG_BLOCKS = (NN + 7) / 8;
    const int GM = NNP / 128;   // 782

    // ---- layer 1: [x | agg(x)] (K=256) -> 256, ReLU; splits only ----
    k_agg<1, 4><<<AGG_BLOCKS, 256>>>(x, hNh, hNl);
    k_mma<256, 256, true, true, 2, true><<<dim3(2, GM), 256, SMB>>>(
        xh, hNh, xl, hNl, W1h, W1l, b1, nullptr, hAh, hAl);

    // ---- layer 2: [hA | agg(hA)] (K=512) -> 256, ReLU; agg reads hi/lo planes ----
    k_agg_hl<<<AGG_BLOCKS, 256>>>(hAh, hAl, hNh, hNl);
    k_mma<256, 512, true, true, 2, true><<<dim3(2, GM), 256, SMB>>>(
        hAh, hNh, hAl, hNl, W2h, W2l, b2, nullptr, hBh, hBl);

    // ---- layer 3 (linear-reordered): z = hB @ [W3_self; W3_neigh]^T, then combine ----
    k_mma<128, 256, false, false, 0, false><<<dim3(1, GM), 256, SMB>>>(
        hBh, hBh, hBl, hBl, W3h, W3l, nullptr, z, nullptr, nullptr);
    k_agg_out<<<AGG_BLOCKS, 256>>>(z, b3, out);
}

// round 16
// speedup vs baseline: 1.1876x; 1.0351x over previous
#include <cuda_runtime.h>
#include <cuda_fp16.h>

#define NN 100000
#define NNP 100096            // padded to multiple of 128 (782 * 128)
#define NE 1600000

// ---- scratch (static device globals; zero-initialized; no allocation allowed) ----
__device__ __half g_xh[NNP * 128];      // x hi/lo (fp16 split, padded)
__device__ __half g_xl[NNP * 128];
__device__ __half g_hNh[NNP * 256];     // aggregated neighbor feats hi/lo
__device__ __half g_hNl[NNP * 256];
__device__ __half g_hAh[NNP * 256];     // layer-1 output hi/lo
__device__ __half g_hAl[NNP * 256];
__device__ __half g_hBh[NNP * 256];     // layer-2 output hi/lo
__device__ __half g_hBl[NNP * 256];
__device__ float  g_z[NNP * 128];       // layer-3 GEMM out: [z_self | z_neigh]
__device__ __half g_W1h[256 * 256];
__device__ __half g_W1l[256 * 256];
__device__ __half g_W2h[256 * 512];
__device__ __half g_W2l[256 * 512];
__device__ __half g_W3h[128 * 256];     // stacked [W3_self; W3_neigh]
__device__ __half g_W3l[128 * 256];
__device__ int   g_deg[NN];             // zero at launch entry (static init +
                                        // re-zeroed by k_csr_mid each launch)
__device__ int   g_rowptr[NN + 1];
__device__ int   g_cursor[NN];
__device__ int   g_csr[NE];

// ======================= helpers =======================

__device__ __forceinline__ void splith(float v, __half& h, __half& l) {
    h = __float2half_rn(v);
    l = __float2half_rn(v - __half2float(h));
}

__device__ __forceinline__ unsigned smem_u32(const void* p) {
    unsigned a;
    asm("{ .reg .u64 t; cvta.to.shared.u64 t, %1; cvt.u32.u64 %0, t; }" : "=r"(a) : "l"(p));
    return a;
}

__device__ __forceinline__ void cp16(unsigned dst, const void* src) {
    asm volatile("cp.async.cg.shared.global [%0], [%1], 16;" :: "r"(dst), "l"(src));
}
#define CP_COMMIT() asm volatile("cp.async.commit_group;" ::: "memory")
#define CP_WAIT1()  asm volatile("cp.async.wait_group 1;" ::: "memory")
#define CP_WAIT0()  asm volatile("cp.async.wait_group 0;" ::: "memory")

__device__ __forceinline__ void mma16(float* c, const unsigned* a, const unsigned* b) {
    asm volatile(
        "mma.sync.aligned.m16n8k16.row.col.f32.f16.f16.f32 "
        "{%0,%1,%2,%3}, {%4,%5,%6,%7}, {%8,%9}, {%0,%1,%2,%3};"
        : "+f"(c[0]), "+f"(c[1]), "+f"(c[2]), "+f"(c[3])
        : "r"(a[0]), "r"(a[1]), "r"(a[2]), "r"(a[3]), "r"(b[0]), "r"(b[1]));
}

__device__ __forceinline__ void ldm_x4(unsigned& r0, unsigned& r1, unsigned& r2,
                                       unsigned& r3, unsigned addr) {
    asm volatile("ldmatrix.sync.aligned.m8n8.x4.shared.b16 {%0,%1,%2,%3}, [%4];"
                 : "=r"(r0), "=r"(r1), "=r"(r2), "=r"(r3) : "r"(addr));
}

// ======================= fused prep: x split, W splits, dst histogram =======================
// g_deg is zero on entry (static init on first launch; re-zeroed by k_csr_mid after).

__global__ void k_prep(const float* __restrict__ x, const float* __restrict__ W1,
                       const float* __restrict__ W2, const float* __restrict__ W3,
                       const int* __restrict__ dst) {
    const int NX = NN * 32;                    // float4 count of x
    long i = (long)blockIdx.x * blockDim.x + threadIdx.x;
    if (i < NX) {
        float4 v = ((const float4*)x)[i];
        __half h0, h1, h2, h3, l0, l1, l2, l3;
        splith(v.x, h0, l0); splith(v.y, h1, l1);
        splith(v.z, h2, l2); splith(v.w, h3, l3);
        ((__half2*)g_xh)[2 * i]     = __halves2half2(h0, h1);
        ((__half2*)g_xh)[2 * i + 1] = __halves2half2(h2, h3);
        ((__half2*)g_xl)[2 * i]     = __halves2half2(l0, l1);
        ((__half2*)g_xl)[2 * i + 1] = __halves2half2(l2, l3);
        return;
    }
    i -= NX;
    if (i < 256 * 256) {                       // W1 full split
        __half h, l; splith(W1[i], h, l);
        g_W1h[i] = h; g_W1l[i] = l;
        return;
    }
    i -= 256 * 256;
    if (i < 256 * 512) {                       // W2 full split
        __half h, l; splith(W2[i], h, l);
        g_W2h[i] = h; g_W2l[i] = l;
        return;
    }
    i -= 256 * 512;
    if (i < 128 * 256) {                       // W3 stacked [self; neigh]
        int r = (int)(i >> 8), c = (int)(i & 255);
        float v = (r < 64) ? W3[r * 512 + c] : W3[(r - 64) * 512 + 256 + c];
        __half h, l; splith(v, h, l);
        g_W3h[i] = h; g_W3l[i] = l;
        return;
    }
    i -= 128 * 256;
    if (i < NE) atomicAdd(&g_deg[dst[i]], 1);  // histogram (overlaps with splits)
}

#define PREP_TOTAL (NN * 32 + 256 * 256 + 256 * 512 + 128 * 256 + NE)

// ======================= CSR mid: scan + fill (+ re-zero deg for next launch) =======================

#define MIDT 1024
#define CH2 ((NN + MIDT - 1) / MIDT)   // 98

__global__ void __launch_bounds__(MIDT)
k_csr_mid() {
    __shared__ int sp[MIDT];
    int t = threadIdx.x;
    int base = t * CH2;
    int end = base + CH2; if (end > NN) end = NN;

    int s = 0;
    for (int i = base; i < end; i++) s += g_deg[i];
    sp[t] = s;
    __syncthreads();

#pragma unroll
    for (int off = 1; off < MIDT; off <<= 1) {
        int v = (t >= off) ? sp[t - off] : 0;
        __syncthreads();
        sp[t] += v;
        __syncthreads();
    }
    int run = sp[t] - s;                       // exclusive prefix
    if (t == MIDT - 1) g_rowptr[NN] = sp[MIDT - 1];

    for (int i = base; i < end; i++) {
        g_rowptr[i] = run;
        g_cursor[i] = run;
        run += g_deg[i];
        g_deg[i] = 0;                          // invariant for next launch
    }
}

__global__ void k_scatter(const int* __restrict__ src, const int* __restrict__ dst) {
    int e = blockIdx.x * blockDim.x + threadIdx.x;
    if (e < NE) {
        int p = atomicAdd(&g_cursor[dst[e]], 1);
        g_csr[p] = src[e];
    }
}

// ======================= aggregation from fp32 source (layer 1) =======================

template <int DV, int UNR>
__global__ void k_agg(const float* __restrict__ h, __half* __restrict__ oh,
                      __half* __restrict__ ol) {
    int gwarp = (blockIdx.x * blockDim.x + threadIdx.x) >> 5;
    int lane = threadIdx.x & 31;
    if (gwarp >= NN) return;

    int s0 = g_rowptr[gwarp];
    int s1 = g_rowptr[gwarp + 1];

    float4 acc[DV];
#pragma unroll
    for (int j = 0; j < DV; j++) acc[j] = make_float4(0.f, 0.f, 0.f, 0.f);

    const int stride4 = DV * 32;
    const float4* __restrict__ hv = (const float4*)h;

    int e = s0;
    for (; e + UNR <= s1; e += UNR) {
        float4 v[UNR][DV];
#pragma unroll
        for (int u = 0; u < UNR; u++) {
            const float4* r = hv + (long)g_csr[e + u] * stride4;
#pragma unroll
            for (int j = 0; j < DV; j++) v[u][j] = r[lane + 32 * j];
        }
#pragma unroll
        for (int u = 0; u < UNR; u++)
#pragma unroll
            for (int j = 0; j < DV; j++) {
                acc[j].x += v[u][j].x; acc[j].y += v[u][j].y;
                acc[j].z += v[u][j].z; acc[j].w += v[u][j].w;
            }
    }
    for (; e < s1; e++) {
        const float4* r = hv + (long)g_csr[e] * stride4;
#pragma unroll
        for (int j = 0; j < DV; j++) {
            float4 v = r[lane + 32 * j];
            acc[j].x += v.x; acc[j].y += v.y; acc[j].z += v.z; acc[j].w += v.w;
        }
    }

    int deg = s1 - s0;
    float inv = 1.0f / (float)(deg > 0 ? deg : 1);
    __half2* ovh = (__half2*)oh + (long)gwarp * (stride4 * 2);
    __half2* ovl = (__half2*)ol + (long)gwarp * (stride4 * 2);
#pragma unroll
    for (int j = 0; j < DV; j++) {
        float4 v;
        v.x = acc[j].x * inv; v.y = acc[j].y * inv;
        v.z = acc[j].z * inv; v.w = acc[j].w * inv;
        __half h0, h1, h2, h3, l0, l1, l2, l3;
        splith(v.x, h0, l0); splith(v.y, h1, l1);
        splith(v.z, h2, l2); splith(v.w, h3, l3);
        int f = lane + 32 * j;
        ovh[2 * f]     = __halves2half2(h0, h1);
        ovh[2 * f + 1] = __halves2half2(h2, h3);
        ovl[2 * f]     = __halves2half2(l0, l1);
        ovl[2 * f + 1] = __halves2half2(l2, l3);
    }
}

// ======================= aggregation from hi/lo fp16 planes (layer 2, 256-dim) =======================
// Reconstructs v = hi + lo per element (error ~2^-22). One warp/node; lane covers 8 elems.
// UNR=2 (round-10 proven; UNR=4 regressed via register pressure).

__device__ __forceinline__ void acc8(float* a, uint4 h, uint4 l) {
    const unsigned* hp = (const unsigned*)&h;
    const unsigned* lp = (const unsigned*)&l;
#pragma unroll
    for (int q = 0; q < 4; q++) {
        float2 fh = __half22float2(*(const __half2*)&hp[q]);
        float2 fl = __half22float2(*(const __half2*)&lp[q]);
        a[2 * q]     += fh.x + fl.x;
        a[2 * q + 1] += fh.y + fl.y;
    }
}

__global__ void k_agg_hl(const __half* __restrict__ hi, const __half* __restrict__ lo,
                         __half* __restrict__ oh, __half* __restrict__ ol) {
    int gwarp = (blockIdx.x * blockDim.x + threadIdx.x) >> 5;
    int lane = threadIdx.x & 31;
    if (gwarp >= NN) return;

    int s0 = g_rowptr[gwarp];
    int s1 = g_rowptr[gwarp + 1];

    float acc[8];
#pragma unroll
    for (int q = 0; q < 8; q++) acc[q] = 0.f;

    const uint4* hv = (const uint4*)hi;        // 32 uint4 per 256-half row
    const uint4* lv = (const uint4*)lo;

    int e = s0;
    for (; e + 2 <= s1; e += 2) {
        long ra = (long)g_csr[e] * 32, rb = (long)g_csr[e + 1] * 32;
        uint4 ha = hv[ra + lane], la = lv[ra + lane];
        uint4 hb = hv[rb + lane], lb = lv[rb + lane];
        acc8(acc, ha, la);
        acc8(acc, hb, lb);
    }
    if (e < s1) {
        long ra = (long)g_csr[e] * 32;
        acc8(acc, hv[ra + lane], lv[ra + lane]);
    }

    int deg = s1 - s0;
    float inv = 1.0f / (float)(deg > 0 ? deg : 1);
    __half2* ovh = (__half2*)oh + (long)gwarp * 128 + lane * 4;
    __half2* ovl = (__half2*)ol + (long)gwarp * 128 + lane * 4;
#pragma unroll
    for (int q = 0; q < 4; q++) {
        float v0 = acc[2 * q] * inv, v1 = acc[2 * q + 1] * inv;
        __half h0, h1, l0, l1;
        splith(v0, h0, l0); splith(v1, h1, l1);
        ovh[q] = __halves2half2(h0, h1);
        ovl[q] = __halves2half2(l0, l1);
    }
}

// ======================= fp16 3-product concat-GEMM (2-stage; peeled final wait) =======================
// C[M, N_OUT] = [A1 | A2] @ W^T (+ bias, optional ReLU), as hi.hi + hi.lo + lo.hi.
// OMODE: 0 = fp32 Cf only, 2 = fp16 splits only.
// The final chunk is computed in a peeled iteration guarded by wait_group 0 —
// wait_group 1 would leave the last committed chunk in flight (round-12 race).

template <int N_OUT, int K, bool CONCAT, bool RELU, int OMODE, bool HAS_BIAS>
__global__ void __launch_bounds__(256, 2)
k_mma(const __half* __restrict__ A1h, const __half* __restrict__ A2h,
      const __half* __restrict__ A1l, const __half* __restrict__ A2l,
      const __half* __restrict__ Wh,  const __half* __restrict__ Wl,
      const float* __restrict__ bias,
      float* __restrict__ Cf, __half* __restrict__ Ch, __half* __restrict__ Cl) {
    constexpr int D = CONCAT ? K / 2 : K;
    constexpr int NCP = K / 64;
    constexpr int NC3 = 3 * NCP;
    constexpr int NT = 8;
    constexpr int SH = 72;
    constexpr int A_BYTES = 128 * SH * 2;      // 18432
    constexpr int STAGE_B = 2 * A_BYTES;

    extern __shared__ char smem_raw[];
    const unsigned sbase = smem_u32(smem_raw);
    const int tid = threadIdx.x;
    const int wid = tid >> 5;
    const int lane = tid & 31;
    const int wm = wid & 3;
    const int wn = wid >> 2;
    const int n0 = blockIdx.x * 128;
    const int m0 = blockIdx.y * 128;

    const int lr = lane >> 2;
    const int lc = lane & 3;

    unsigned offA[2], offB[4];
#pragma unroll
    for (int mt = 0; mt < 2; mt++) {
        int row = wm * 32 + mt * 16 + (lane & 15);
        int col = (lane >> 4) * 8;
        offA[mt] = (unsigned)(row * SH + col) * 2;
    }
#pragma unroll
    for (int p = 0; p < 4; p++) {
        int row = wn * 64 + p * 16 + (lane & 7) + ((lane >> 4) & 1) * 8;
        int col = ((lane >> 3) & 1) * 8;
        offB[p] = (unsigned)(A_BYTES) + (unsigned)(row * SH + col) * 2;
    }

    float acc[2][NT][4];
#pragma unroll
    for (int mt = 0; mt < 2; mt++)
#pragma unroll
        for (int nt = 0; nt < NT; nt++)
#pragma unroll
            for (int q = 0; q < 4; q++) acc[mt][nt][q] = 0.f;

    auto load_chunk = [&](int j, int s) {
        unsigned base = sbase + s * STAGE_B;
        int p = j / NCP;                       // 0: hi.hi, 1: hi.lo, 2: lo.hi
        int k0 = (j - p * NCP) * 64;
        const __half* A;
        int ka;
        if (CONCAT && k0 >= D) {
            A = (p < 2) ? A2h : A2l; ka = k0 - D;
        } else {
            A = (p < 2) ? A1h : A1l; ka = k0;
        }
        const __half* B = (p == 1) ? Wl : Wh;
#pragma unroll
        for (int q = 0; q < 4; q++) {
            int idx = tid + 256 * q;
            int row = idx >> 3, c8 = idx & 7;
            cp16(base + (unsigned)(row * (SH * 2) + c8 * 16),
                 A + (long)(m0 + row) * D + ka + c8 * 8);
        }
#pragma unroll
        for (int q = 0; q < 4; q++) {
            int idx = tid + 256 * q;
            int n = idx >> 3, c8 = idx & 7;
            cp16(base + (unsigned)(A_BYTES + n * (SH * 2) + c8 * 16),
                 B + (long)(n0 + n) * K + k0 + c8 * 8);
        }
        CP_COMMIT();
    };

    auto compute_chunk = [&](unsigned stage) {
#pragma unroll
        for (int ks = 0; ks < 4; ks++) {
            unsigned kso = ks * 32;
            unsigned a[2][4];
#pragma unroll
            for (int mt = 0; mt < 2; mt++)
                ldm_x4(a[mt][0], a[mt][1], a[mt][2], a[mt][3],
                       stage + offA[mt] + kso);
            unsigned b[NT][2];
#pragma unroll
            for (int p = 0; p < 4; p++)
                ldm_x4(b[2 * p][0], b[2 * p][1], b[2 * p + 1][0], b[2 * p + 1][1],
                       stage + offB[p] + kso);
#pragma unroll
            for (int mt = 0; mt < 2; mt++)
#pragma unroll
                for (int nt = 0; nt < NT; nt++)
                    mma16(acc[mt][nt], a[mt], b[nt]);
        }
    };

    load_chunk(0, 0);
    load_chunk(1, 1);

#pragma unroll 1
    for (int i = 0; i < NC3 - 1; i++) {
        int s = i & 1;
        CP_WAIT1();
        __syncthreads();
        compute_chunk(sbase + s * STAGE_B);
        __syncthreads();
        if (i + 2 < NC3) load_chunk(i + 2, s);
    }
    // peeled final chunk: must drain ALL outstanding groups
    CP_WAIT0();
    __syncthreads();
    compute_chunk(sbase + ((NC3 - 1) & 1) * STAGE_B);

    // epilogue
#pragma unroll
    for (int mt = 0; mt < 2; mt++) {
#pragma unroll
        for (int nt = 0; nt < NT; nt++) {
            int n = n0 + wn * 64 + nt * 8 + lc * 2;
            float b0 = 0.f, b1 = 0.f;
            if (HAS_BIAS) { b0 = bias[n]; b1 = bias[n + 1]; }
            int r0 = m0 + wm * 32 + mt * 16 + lr;
#pragma unroll
            for (int h = 0; h < 2; h++) {
                int r = r0 + h * 8;
                if (r < NN) {
                    long off = (long)r * N_OUT + n;
                    float v0 = acc[mt][nt][2 * h + 0] + b0;
                    float v1 = acc[mt][nt][2 * h + 1] + b1;
                    if (RELU) { v0 = v0 > 0.f ? v0 : 0.f; v1 = v1 > 0.f ? v1 : 0.f; }
                    if (OMODE == 0) {
                        *(float2*)(Cf + off) = make_float2(v0, v1);
                    } else {
                        __half h0, h1, l0, l1;
                        splith(v0, h0, l0); splith(v1, h1, l1);
                        ((__half2*)Ch)[off >> 1] = __halves2half2(h0, h1);
                        ((__half2*)Cl)[off >> 1] = __halves2half2(l0, l1);
                    }
                }
            }
        }
    }
}

// ======================= layer-3 final: out = z_self + mean(z_neigh) + b =======================

__global__ void k_agg_out(const float* __restrict__ z, const float* __restrict__ b3,
                          float* __restrict__ out) {
    int gwarp = (blockIdx.x * blockDim.x + threadIdx.x) >> 5;
    int lane = threadIdx.x & 31;
    if (gwarp >= NN) return;

    int s0 = g_rowptr[gwarp];
    int s1 = g_rowptr[gwarp + 1];

    float2 acc = make_float2(0.f, 0.f);
    const float2* zn = (const float2*)(z + 64);
    int e = s0;
    for (; e + 3 < s1; e += 4) {
        float2 v0 = zn[(long)g_csr[e] * 64 + lane];
        float2 v1 = zn[(long)g_csr[e + 1] * 64 + lane];
        float2 v2 = zn[(long)g_csr[e + 2] * 64 + lane];
        float2 v3 = zn[(long)g_csr[e + 3] * 64 + lane];
        acc.x += (v0.x + v1.x) + (v2.x + v3.x);
        acc.y += (v0.y + v1.y) + (v2.y + v3.y);
    }
    for (; e < s1; e++) {
        float2 v = zn[(long)g_csr[e] * 64 + lane];
        acc.x += v.x; acc.y += v.y;
    }
    int deg = s1 - s0;
    float inv = 1.0f / (float)(deg > 0 ? deg : 1);

    float2 self = ((const float2*)z)[(long)gwarp * 64 + lane];
    float2 bb = ((const float2*)b3)[lane];
    float2 r;
    r.x = self.x + acc.x * inv + bb.x;
    r.y = self.y + acc.y * inv + bb.y;
    ((float2*)out)[(long)gwarp * 32 + lane] = r;
}

// ======================= launch =======================

extern "C" void kernel_launch(void* const* d_in, const int* in_sizes, int n_in,
                              void* d_out, int out_size) {
    const float* x   = (const float*)d_in[0];
    const int*   src = (const int*)d_in[1];
    const int*   dst = (const int*)d_in[2];
    const float* W1  = (const float*)d_in[3];
    const float* b1  = (const float*)d_in[4];
    const float* W2  = (const float*)d_in[5];
    const float* b2  = (const float*)d_in[6];
    const float* W3  = (const float*)d_in[7];
    const float* b3  = (const float*)d_in[8];
    float* out = (float*)d_out;

    __half *xh, *xl, *hNh, *hNl, *hAh, *hAl, *hBh, *hBl;
    __half *W1h, *W1l, *W2h, *W2l, *W3h, *W3l;
    float *z;
    cudaGetSymbolAddress((void**)&xh, g_xh);
    cudaGetSymbolAddress((void**)&xl, g_xl);
    cudaGetSymbolAddress((void**)&hNh, g_hNh);
    cudaGetSymbolAddress((void**)&hNl, g_hNl);
    cudaGetSymbolAddress((void**)&hAh, g_hAh);
    cudaGetSymbolAddress((void**)&hAl, g_hAl);
    cudaGetSymbolAddress((void**)&hBh, g_hBh);
    cudaGetSymbolAddress((void**)&hBl, g_hBl);
    cudaGetSymbolAddress((void**)&z, g_z);
    cudaGetSymbolAddress((void**)&W1h, g_W1h);
    cudaGetSymbolAddress((void**)&W1l, g_W1l);
    cudaGetSymbolAddress((void**)&W2h, g_W2h);
    cudaGetSymbolAddress((void**)&W2l, g_W2l);
    cudaGetSymbolAddress((void**)&W3h, g_W3h);
    cudaGetSymbolAddress((void**)&W3l, g_W3l);

    constexpr int SMB = 2 * 2 * 128 * 72 * 2;   // 73728
    cudaFuncSetAttribute(k_mma<256, 256, true,  true,  2, true>,
                         cudaFuncAttributeMaxDynamicSharedMemorySize, SMB);
    cudaFuncSetAttribute(k_mma<256, 512, true,  true,  2, true>,
                         cudaFuncAttributeMaxDynamicSharedMemorySize, SMB);
    cudaFuncSetAttribute(k_mma<128, 256, false, false, 0, false>,
                         cudaFuncAttributeMaxDynamicSharedMemorySize, SMB);

    // --- fused prep (splits + histogram) + CSR build, all serial (proven fastest) ---
    k_prep<<<(PREP_TOTAL + 255) / 256, 256>>>(x, W1, W2, W3, dst);
    k_csr_mid<<<1, MIDT>>>();
    k_scatter<<<(NE + 255) / 256, 256>>>(src, dst);

    const int AGG_BLOCKS = (NN + 7) / 8;
    const int GM = NNP / 128;   // 782

    // ---- layer 1: [x | agg(x)] (K=256) -> 256, ReLU; splits only ----
    k_agg<1, 4><<<AGG_BLOCKS, 256>>>(x, hNh, hNl);
    k_mma<256, 256, true, true, 2, true><<<dim3(2, GM), 256, SMB>>>(
        xh, hNh, xl, hNl, W1h, W1l, b1, nullptr, hAh, hAl);

    // ---- layer 2: [hA | agg(hA)] (K=512) -> 256, ReLU; agg reads hi/lo planes ----
    k_agg_hl<<<AGG_BLOCKS, 256>>>(hAh, hAl, hNh, hNl);
    k_mma<256, 512, true, true, 2, true><<<dim3(2, GM), 256, SMB>>>(
        hAh, hNh, hAl, hNl, W2h, W2l, b2, nullptr, hBh, hBl);

    // ---- layer 3 (linear-reordered): z = hB @ [W3_self; W3_neigh]^T, then combine ----
    k_mma<128, 256, false, false, 0, false><<<dim3(1, GM), 256, SMB>>>(
        hBh, hBh, hBl, hBl, W3h, W3l, nullptr, z, nullptr, nullptr);
    k_agg_out<<<AGG_BLOCKS, 256>>>(z, b3, out);
}